// round 6
// baseline (speedup 1.0000x reference)
#include <cuda_runtime.h>

#define NB       262144
#define ZDIM     128
#define ZH       64
#define HS       50
#define HSP      52                      // HS padded to 52 floats (16B rows)
#define NSTAGE   4
#define NTHREADS 512                     // 4 lanes per row, 128 rows/CTA
#define GRID     2048                    // NB*4 / NTHREADS exactly

// quarter-skewed row offset: row r lives at r*HSP + (r>>4)*4 floats
// (each 16-row quarter shifted by 16B so the 4 broadcast groups are bank-disjoint)
#define QSTRIDE  (16*HSP + 4)            // 836 floats per quarter block
#define STG_W    (4*QSTRIDE)             // 3344 floats per stage per matrix

// SMEM layout (float offsets)
#define W0T_OFF  0                        // [s][k][j] transposed W_in, quarter-skewed
#define WMU_OFF  (NSTAGE*STG_W)           // [s][o][j] quarter-skewed
#define WSIG_OFF (2*NSTAGE*STG_W)
#define BIN_OFF  (3*NSTAGE*STG_W)         // [s][HSP]
#define BMU_OFF  (BIN_OFF + NSTAGE*HSP)   // [s][68]  index oo = o + (o>>4)
#define BSIG_OFF (BMU_OFF + NSTAGE*68)
#define SMEM_FLOATS (BSIG_OFF + NSTAGE*68)    // 40880
#define SMEM_BYTES  (SMEM_FLOATS*4)           // 163520

typedef unsigned long long ull;

__device__ __forceinline__ ull pack2(float lo, float hi) {
    ull r; asm("mov.b64 %0,{%1,%2};" : "=l"(r) : "f"(lo), "f"(hi)); return r;
}
__device__ __forceinline__ void unpack2(ull v, float &lo, float &hi) {
    asm("mov.b64 {%0,%1},%2;" : "=f"(lo), "=f"(hi) : "l"(v));
}
__device__ __forceinline__ void fma2(ull &d, ull a, ull b) {
    asm("fma.rn.f32x2 %0,%1,%2,%0;" : "+l"(d) : "l"(a), "l"(b));
}
__device__ __forceinline__ void add2(ull &d, ull a) {
    asm("add.rn.f32x2 %0,%0,%1;" : "+l"(d) : "l"(a));
}
__device__ __forceinline__ float rcpa(float x) {
    float r; asm("rcp.approx.f32 %0,%1;" : "=f"(r) : "f"(x)); return r;
}

// One coupling half-step, 4-lane cooperative (lanes q=0..3 of a row group).
// Thread owns zin[16] (k = q*16+kl) and updates zout[16] (o = q*16+ol).
__device__ __forceinline__ void coupling(
    const float (&zin)[16], float (&zout)[16], const int q,
    const float* __restrict__ w0t_s, const float* __restrict__ wmu_s,
    const float* __restrict__ wsig_s, const float* __restrict__ bin_s,
    const float* __restrict__ bmu_s,  const float* __restrict__ bsig_s,
    float &logdet)
{
    ull hp[26];
    {   // bias added by q==0 only (summed in the butterfly below)
        const ull* b2 = (const ull*)bin_s;            // uniform addr -> broadcast
#pragma unroll
        for (int p = 0; p < 26; p++) hp[p] = (q == 0) ? b2[p] : 0ull;
    }
    // partial h over own 16 k's (outer-product; zin stays in registers)
    {
        const float* wb = w0t_s + q*QSTRIDE;
#pragma unroll
        for (int kl = 0; kl < 16; kl++) {
            ull zz = pack2(zin[kl], zin[kl]);
            const ulonglong2* wr = (const ulonglong2*)(wb + kl*HSP);
#pragma unroll
            for (int p = 0; p < 13; p++) {
                ulonglong2 w = wr[p];
                fma2(hp[2*p + 0], zz, w.x);
                fma2(hp[2*p + 1], zz, w.y);
            }
        }
    }
    // 2-stage butterfly reduce across the 4-lane group
#pragma unroll
    for (int p = 0; p < 26; p++) {
        ull a = __shfl_xor_sync(0xffffffffu, hp[p], 1); add2(hp[p], a);
        ull b = __shfl_xor_sync(0xffffffffu, hp[p], 2); add2(hp[p], b);
    }
    // tanh: even lanes take hp[0..12], odd lanes hp[13..25]; exchange via xor-1
    {
        const int hi = q & 1;
#pragma unroll
        for (int i = 0; i < 13; i++) {
            const int own = hi ? 13 + i : i;
            const int oth = hi ? i : 13 + i;
            float a, b; unpack2(hp[own], a, b);
            ull tt = pack2(tanhf(a), tanhf(b));       // pad lanes: tanh(0)=0
            ull peer = __shfl_xor_sync(0xffffffffu, tt, 1);
            hp[own] = tt;
            hp[oth] = peer;
        }
    }
    // mu / sig for own 16 outputs
    const float* wm_b = wmu_s  + q*QSTRIDE;
    const float* ws_b = wsig_s + q*QSTRIDE;
    const float* bm_h = bmu_s  + q*17;
    const float* bs_h = bsig_s + q*17;
#pragma unroll
    for (int ol = 0; ol < 16; ol++) {
        ull am0 = 0ull, am1 = 0ull, as0 = 0ull, as1 = 0ull;
        const ulonglong2* wm = (const ulonglong2*)(wm_b + ol*HSP);
        const ulonglong2* ws = (const ulonglong2*)(ws_b + ol*HSP);
#pragma unroll
        for (int p = 0; p < 13; p++) {
            ulonglong2 a = wm[p];
            fma2(am0, hp[2*p + 0], a.x);
            fma2(am1, hp[2*p + 1], a.y);
            ulonglong2 b = ws[p];
            fma2(as0, hp[2*p + 0], b.x);
            fma2(as1, hp[2*p + 1], b.y);
        }
        float m0,m1,m2,m3, s0,s1,s2,s3;
        unpack2(am0, m0, m1); unpack2(am1, m2, m3);
        unpack2(as0, s0, s1); unpack2(as1, s2, s3);
        float mu = bm_h[ol] + ((m0 + m1) + (m2 + m3));
        float t  = bs_h[ol] + ((s0 + s1) + (s2 + s3));
        float e  = __expf(-t);                        // MUFU.EX2
        float u  = 1.0f + e;
        float sig = rcpa(u);                          // MUFU.RCP
        zout[ol] = zout[ol] * sig + mu;
        logdet  -= __logf(u);                         // log(sig) = -log(1+e), MUFU.LG2
    }
}

__global__ void __launch_bounds__(NTHREADS, 1) flow_kernel(
    const float* __restrict__ g_mean, const float* __restrict__ g_logvar,
    const float* __restrict__ g_eps,
    const float* __restrict__ g_Win,  const float* __restrict__ g_bin,
    const float* __restrict__ g_Wmu,  const float* __restrict__ g_bmu,
    const float* __restrict__ g_Wsig, const float* __restrict__ g_bsig,
    float* __restrict__ g_out)
{
    extern __shared__ float sm[];
    const int tid = threadIdx.x;

    // zero (covers pads/skew gaps), then stage all weights in SMEM
    for (int i = tid; i < SMEM_FLOATS; i += NTHREADS) sm[i] = 0.f;
    __syncthreads();
    for (int i = tid; i < NSTAGE*HS*ZH; i += NTHREADS) {   // W_in -> [s][k][j], skewed
        int s = i / (HS*ZH); int r = i - s*(HS*ZH);
        int j = r / ZH;      int k = r - j*ZH;
        sm[W0T_OFF + s*STG_W + k*HSP + (k>>4)*4 + j] = g_Win[i];
    }
    for (int i = tid; i < NSTAGE*ZH*HS; i += NTHREADS) {   // W_mu/W_sig -> [s][o][j], skewed
        int s = i / (ZH*HS); int r = i - s*(ZH*HS);
        int o = r / HS;      int j = r - o*HS;
        int off = s*STG_W + o*HSP + (o>>4)*4 + j;
        sm[WMU_OFF  + off] = g_Wmu[i];
        sm[WSIG_OFF + off] = g_Wsig[i];
    }
    for (int i = tid; i < NSTAGE*HS; i += NTHREADS) {
        int s = i / HS; int j = i - s*HS;
        sm[BIN_OFF + s*HSP + j] = g_bin[i];
    }
    for (int i = tid; i < NSTAGE*ZH; i += NTHREADS) {
        int s = i / ZH; int o = i - s*ZH;
        int oo = o + (o >> 4);                              // 17-stride quarters
        sm[BMU_OFF  + s*68 + oo] = g_bmu[i];
        sm[BSIG_OFF + s*68 + oo] = g_bsig[i];
    }
    __syncthreads();

    const int gt  = blockIdx.x * NTHREADS + tid;
    const int row = gt >> 2;
    const int q   = gt & 3;

    // load own quarter-row pieces: z1 quarter and z2 quarter
    const size_t rb = (size_t)row * ZDIM;
    const float4* m1 = (const float4*)(g_mean   + rb + q*16);
    const float4* l1 = (const float4*)(g_logvar + rb + q*16);
    const float4* e1 = (const float4*)(g_eps    + rb + q*16);
    const float4* m2 = (const float4*)(g_mean   + rb + 64 + q*16);
    const float4* l2 = (const float4*)(g_logvar + rb + 64 + q*16);
    const float4* e2 = (const float4*)(g_eps    + rb + 64 + q*16);

    float z1[16], z2[16];
    float slv = 0.f, se2 = 0.f;
#pragma unroll
    for (int i = 0; i < 4; i++) {
        float4 m = m1[i], l = l1[i], e = e1[i];
        z1[4*i+0] = e.x * __expf(0.5f*l.x) + m.x;
        z1[4*i+1] = e.y * __expf(0.5f*l.y) + m.y;
        z1[4*i+2] = e.z * __expf(0.5f*l.z) + m.z;
        z1[4*i+3] = e.w * __expf(0.5f*l.w) + m.w;
        slv += (l.x + l.y) + (l.z + l.w);
        se2 += (e.x*e.x + e.y*e.y) + (e.z*e.z + e.w*e.w);
    }
#pragma unroll
    for (int i = 0; i < 4; i++) {
        float4 m = m2[i], l = l2[i], e = e2[i];
        z2[4*i+0] = e.x * __expf(0.5f*l.x) + m.x;
        z2[4*i+1] = e.y * __expf(0.5f*l.y) + m.y;
        z2[4*i+2] = e.z * __expf(0.5f*l.z) + m.z;
        z2[4*i+3] = e.w * __expf(0.5f*l.w) + m.w;
        slv += (l.x + l.y) + (l.z + l.w);
        se2 += (e.x*e.x + e.y*e.y) + (e.z*e.z + e.w*e.w);
    }
    // (z-mean)^2/exp(logvar) == eps^2 exactly
    float part = slv + se2;                 // per-thread partial of -2*logqz0
    float logdet = 0.f;

#pragma unroll 1   // keep flow loop rolled: bounds I-cache footprint
    for (int f = 0; f < 2; f++) {
        {
            const int s = 2*f;
            coupling(z1, z2, q,
                     sm + W0T_OFF + s*STG_W, sm + WMU_OFF + s*STG_W,
                     sm + WSIG_OFF + s*STG_W, sm + BIN_OFF + s*HSP,
                     sm + BMU_OFF + s*68, sm + BSIG_OFF + s*68, logdet);
        }
        {
            const int s = 2*f + 1;
            coupling(z2, z1, q,
                     sm + W0T_OFF + s*STG_W, sm + WMU_OFF + s*STG_W,
                     sm + WSIG_OFF + s*STG_W, sm + BIN_OFF + s*HSP,
                     sm + BMU_OFF + s*68, sm + BSIG_OFF + s*68, logdet);
        }
    }

    // epilogue: write z, reduce logpz / logqz across the 4-lane group
    float sq = 0.f;
    float4* o1 = (float4*)(g_out + rb + q*16);
    float4* o2 = (float4*)(g_out + rb + 64 + q*16);
#pragma unroll
    for (int i = 0; i < 4; i++) {
        float a = z1[4*i+0], b = z1[4*i+1], c = z1[4*i+2], d = z1[4*i+3];
        o1[i] = make_float4(a, b, c, d);
        sq += (a*a + b*b) + (c*c + d*d);
    }
#pragma unroll
    for (int i = 0; i < 4; i++) {
        float a = z2[4*i+0], b = z2[4*i+1], c = z2[4*i+2], d = z2[4*i+3];
        o2[i] = make_float4(a, b, c, d);
        sq += (a*a + b*b) + (c*c + d*d);
    }
    sq     += __shfl_xor_sync(0xffffffffu, sq, 1);
    sq     += __shfl_xor_sync(0xffffffffu, sq, 2);
    part   += __shfl_xor_sync(0xffffffffu, part, 1);
    part   += __shfl_xor_sync(0xffffffffu, part, 2);
    logdet += __shfl_xor_sync(0xffffffffu, logdet, 1);
    logdet += __shfl_xor_sync(0xffffffffu, logdet, 2);
    if (q == 0) {
        g_out[(size_t)NB*ZDIM + row]      = -0.5f * sq;            // logpz
        g_out[(size_t)NB*ZDIM + NB + row] = -0.5f * part - logdet; // logqz
    }
}

extern "C" void kernel_launch(void* const* d_in, const int* in_sizes, int n_in,
                              void* d_out, int out_size)
{
    (void)in_sizes; (void)n_in; (void)out_size;
    cudaFuncSetAttribute(flow_kernel,
                         cudaFuncAttributeMaxDynamicSharedMemorySize, SMEM_BYTES);
    flow_kernel<<<GRID, NTHREADS, SMEM_BYTES>>>(
        (const float*)d_in[0], (const float*)d_in[1], (const float*)d_in[2],
        (const float*)d_in[3], (const float*)d_in[4], (const float*)d_in[5],
        (const float*)d_in[6], (const float*)d_in[7], (const float*)d_in[8],
        (float*)d_out);
}

// round 7
// speedup vs baseline: 1.3885x; 1.3885x over previous
#include <cuda_runtime.h>

#define NB       262144
#define ZDIM     128
#define ZH       64
#define HS       50
#define HSP      56                      // padded: two 28-float (112B) j-halves
#define NSTAGE   4
#define NTHREADS 448                     // 2 lanes per row, 224 rows/CTA, 14 warps
#define GRID     1171                    // ceil(NB/224)

#define STG_W    (ZH*HSP)                // 3584 floats per stage per matrix

// SMEM layout (float offsets)
#define W0T_OFF  0                        // [s][k][j]  (transposed W_in)
#define WMU_OFF  (NSTAGE*STG_W)           // [s][o][j]
#define WSIG_OFF (2*NSTAGE*STG_W)
#define BIN_OFF  (3*NSTAGE*STG_W)         // [s][HSP]
#define BMU_OFF  (BIN_OFF + NSTAGE*HSP)   // [s][66]: o -> o + (o>=32)
#define BSIG_OFF (BMU_OFF + NSTAGE*66)
#define SMEM_FLOATS (BSIG_OFF + NSTAGE*66)   // 43760
#define SMEM_BYTES  (SMEM_FLOATS*4)          // 175040

typedef unsigned long long ull;

__device__ __forceinline__ ull pack2(float lo, float hi) {
    ull r; asm("mov.b64 %0,{%1,%2};" : "=l"(r) : "f"(lo), "f"(hi)); return r;
}
__device__ __forceinline__ void unpack2(ull v, float &lo, float &hi) {
    asm("mov.b64 {%0,%1},%2;" : "=f"(lo), "=f"(hi) : "l"(v));
}
__device__ __forceinline__ void fma2(ull &d, ull a, ull b) {
    asm("fma.rn.f32x2 %0,%1,%2,%0;" : "+l"(d) : "l"(a), "l"(b));
}
__device__ __forceinline__ float rcpa(float x) {
    float r; asm("rcp.approx.f32 %0,%1;" : "=f"(r) : "f"(x)); return r;
}
__device__ __forceinline__ float hsum4(ull a, ull b) {
    float x0,x1,x2,x3; unpack2(a,x0,x1); unpack2(b,x2,x3);
    return (x0+x1)+(x2+x3);
}

// One coupling half-step, lane-pair cooperative with j-split h.
// Lane q owns zin[32] (k = q*32+kl), zout[32] (o = q*32+ol), and h-half
// j in [q*28, q*28+28) (j >= 50 are zero pads).
__device__ __forceinline__ void coupling(
    const float (&zin)[32], float (&zout)[32], const int q,
    const float* __restrict__ w0t_s, const float* __restrict__ wmu_s,
    const float* __restrict__ wsig_s, const float* __restrict__ bin_s,
    const float* __restrict__ bmu_s,  const float* __restrict__ bsig_s,
    float &logdet)
{
    // init h-half with bias (own half; broadcast pair of addresses, bank-disjoint)
    ull h[14];
    {
        const ulonglong2* bh = (const ulonglong2*)(bin_s + q*28);
#pragma unroll
        for (int p = 0; p < 7; p++) { ulonglong2 b = bh[p]; h[2*p] = b.x; h[2*p+1] = b.y; }
    }
    // phase 1: accumulate over ALL 64 k for own j-half.
    // Peer z-values arrive via one packed shfl per z-pair.
    {
        const float* wb = w0t_s + q*28;
#pragma unroll
        for (int i = 0; i < 16; i++) {
            ull mine = pack2(zin[2*i], zin[2*i+1]);
            ull recv = __shfl_xor_sync(0xffffffffu, mine, 1);
            float a0,a1,b0,b1;                       // k=2i,2i+1 and k=32+2i,33+2i
            unpack2(q ? recv : mine, a0, a1);
            unpack2(q ? mine : recv, b0, b1);
            const ulonglong2* r0 = (const ulonglong2*)(wb + (2*i    )*HSP);
            const ulonglong2* r1 = (const ulonglong2*)(wb + (2*i + 1)*HSP);
            const ulonglong2* r2 = (const ulonglong2*)(wb + (32+2*i  )*HSP);
            const ulonglong2* r3 = (const ulonglong2*)(wb + (33+2*i  )*HSP);
            ull zA0 = pack2(a0,a0), zA1 = pack2(a1,a1);
            ull zB0 = pack2(b0,b0), zB1 = pack2(b1,b1);
#pragma unroll
            for (int p = 0; p < 7; p++) {
                ulonglong2 w0 = r0[p]; fma2(h[2*p], zA0, w0.x); fma2(h[2*p+1], zA0, w0.y);
                ulonglong2 w1 = r1[p]; fma2(h[2*p], zA1, w1.x); fma2(h[2*p+1], zA1, w1.y);
                ulonglong2 w2 = r2[p]; fma2(h[2*p], zB0, w2.x); fma2(h[2*p+1], zB0, w2.y);
                ulonglong2 w3 = r3[p]; fma2(h[2*p], zB1, w3.x); fma2(h[2*p+1], zB1, w3.y);
            }
        }
    }
    // tanh on own half only (pads: tanh(0)=0, pad weights are 0)
#pragma unroll
    for (int p = 0; p < 14; p++) {
        float a, b; unpack2(h[p], a, b);
        h[p] = pack2(tanhf(a), tanhf(b));
    }
    // phase 2: per step, half-dots for own output (o=q*32+i) and peer output
    // (o=(1-q)*32+i) over own j-half; one packed shfl merges cross partials.
    const float* wmq = wmu_s  + q*28;
    const float* wsq = wsig_s + q*28;
    const float* bm  = bmu_s  + q*33;
    const float* bs  = bsig_s + q*33;
    int own_row  = (q*32) * HSP;
    int peer_row = ((1-q)*32) * HSP;
#pragma unroll 4
    for (int i = 0; i < 32; i++) {
        ull am0=0ull, am1=0ull, as0=0ull, as1=0ull;   // own output partials
        ull xm0=0ull, xm1=0ull, xs0=0ull, xs1=0ull;   // peer output partials
        const ulonglong2* wmo = (const ulonglong2*)(wmq + own_row);
        const ulonglong2* wso = (const ulonglong2*)(wsq + own_row);
        const ulonglong2* wmp = (const ulonglong2*)(wmq + peer_row);
        const ulonglong2* wsp = (const ulonglong2*)(wsq + peer_row);
#pragma unroll
        for (int p = 0; p < 7; p++) {
            ulonglong2 a = wmo[p]; fma2(am0, h[2*p], a.x); fma2(am1, h[2*p+1], a.y);
            ulonglong2 b = wso[p]; fma2(as0, h[2*p], b.x); fma2(as1, h[2*p+1], b.y);
            ulonglong2 c = wmp[p]; fma2(xm0, h[2*p], c.x); fma2(xm1, h[2*p+1], c.y);
            ulonglong2 d = wsp[p]; fma2(xs0, h[2*p], d.x); fma2(xs1, h[2*p+1], d.y);
        }
        float mu_o = hsum4(am0, am1);
        float tg_o = hsum4(as0, as1);
        float mu_x = hsum4(xm0, xm1);
        float tg_x = hsum4(xs0, xs1);
        ull rec = __shfl_xor_sync(0xffffffffu, pack2(mu_x, tg_x), 1);
        float rmu, rtg; unpack2(rec, rmu, rtg);
        float mu = bm[i] + (mu_o + rmu);
        float t  = bs[i] + (tg_o + rtg);
        float e  = __expf(-t);                        // MUFU.EX2
        float u  = 1.0f + e;
        float sig = rcpa(u);                          // MUFU.RCP
        zout[i] = zout[i] * sig + mu;
        logdet -= __logf(u);                          // log(sigmoid) = -log(1+e)
        own_row  += HSP;
        peer_row += HSP;
    }
}

__global__ void __launch_bounds__(NTHREADS, 1) flow_kernel(
    const float* __restrict__ g_mean, const float* __restrict__ g_logvar,
    const float* __restrict__ g_eps,
    const float* __restrict__ g_Win,  const float* __restrict__ g_bin,
    const float* __restrict__ g_Wmu,  const float* __restrict__ g_bmu,
    const float* __restrict__ g_Wsig, const float* __restrict__ g_bsig,
    float* __restrict__ g_out)
{
    extern __shared__ float sm[];
    const int tid = threadIdx.x;

    // zero (covers j-pads), then stage all weights in SMEM
    for (int i = tid; i < SMEM_FLOATS; i += NTHREADS) sm[i] = 0.f;
    __syncthreads();
    for (int i = tid; i < NSTAGE*HS*ZH; i += NTHREADS) {   // W_in -> [s][k][j]
        int s = i / (HS*ZH); int r = i - s*(HS*ZH);
        int j = r / ZH;      int k = r - j*ZH;
        sm[W0T_OFF + s*STG_W + k*HSP + j] = g_Win[i];
    }
    for (int i = tid; i < NSTAGE*ZH*HS; i += NTHREADS) {   // W_mu/W_sig -> [s][o][j]
        int s = i / (ZH*HS); int r = i - s*(ZH*HS);
        int o = r / HS;      int j = r - o*HS;
        int off = s*STG_W + o*HSP + j;
        sm[WMU_OFF  + off] = g_Wmu[i];
        sm[WSIG_OFF + off] = g_Wsig[i];
    }
    for (int i = tid; i < NSTAGE*HS; i += NTHREADS) {
        int s = i / HS; int j = i - s*HS;
        sm[BIN_OFF + s*HSP + j] = g_bin[i];
    }
    for (int i = tid; i < NSTAGE*ZH; i += NTHREADS) {
        int s = i / ZH; int o = i - s*ZH;
        int oo = o + (o >> 5);                              // halves at 33-stride
        sm[BMU_OFF  + s*66 + oo] = g_bmu[i];
        sm[BSIG_OFF + s*66 + oo] = g_bsig[i];
    }
    __syncthreads();

    const int gt  = blockIdx.x * NTHREADS + tid;
    const int row = gt >> 1;
    const int q   = gt & 1;
    if (row >= NB) return;               // whole-warp exits (16 rows per warp)

    // load own quarter-row pieces: z1 half and z2 half
    const size_t rb = (size_t)row * ZDIM;
    const float4* m1 = (const float4*)(g_mean   + rb + q*32);
    const float4* l1 = (const float4*)(g_logvar + rb + q*32);
    const float4* e1 = (const float4*)(g_eps    + rb + q*32);
    const float4* m2 = (const float4*)(g_mean   + rb + 64 + q*32);
    const float4* l2 = (const float4*)(g_logvar + rb + 64 + q*32);
    const float4* e2 = (const float4*)(g_eps    + rb + 64 + q*32);

    float z1[32], z2[32];
    float slv = 0.f, se2 = 0.f;
#pragma unroll
    for (int i = 0; i < 8; i++) {
        float4 m = m1[i], l = l1[i], e = e1[i];
        z1[4*i+0] = e.x * __expf(0.5f*l.x) + m.x;
        z1[4*i+1] = e.y * __expf(0.5f*l.y) + m.y;
        z1[4*i+2] = e.z * __expf(0.5f*l.z) + m.z;
        z1[4*i+3] = e.w * __expf(0.5f*l.w) + m.w;
        slv += (l.x + l.y) + (l.z + l.w);
        se2 += (e.x*e.x + e.y*e.y) + (e.z*e.z + e.w*e.w);
    }
#pragma unroll
    for (int i = 0; i < 8; i++) {
        float4 m = m2[i], l = l2[i], e = e2[i];
        z2[4*i+0] = e.x * __expf(0.5f*l.x) + m.x;
        z2[4*i+1] = e.y * __expf(0.5f*l.y) + m.y;
        z2[4*i+2] = e.z * __expf(0.5f*l.z) + m.z;
        z2[4*i+3] = e.w * __expf(0.5f*l.w) + m.w;
        slv += (l.x + l.y) + (l.z + l.w);
        se2 += (e.x*e.x + e.y*e.y) + (e.z*e.z + e.w*e.w);
    }
    // (z-mean)^2/exp(logvar) == eps^2 exactly
    float part = slv + se2;                 // per-thread partial of -2*logqz0
    float logdet = 0.f;

#pragma unroll 1   // keep flow loop rolled: bounds I-cache footprint
    for (int f = 0; f < 2; f++) {
        {
            const int s = 2*f;
            coupling(z1, z2, q,
                     sm + W0T_OFF + s*STG_W, sm + WMU_OFF + s*STG_W,
                     sm + WSIG_OFF + s*STG_W, sm + BIN_OFF + s*HSP,
                     sm + BMU_OFF + s*66, sm + BSIG_OFF + s*66, logdet);
        }
        {
            const int s = 2*f + 1;
            coupling(z2, z1, q,
                     sm + W0T_OFF + s*STG_W, sm + WMU_OFF + s*STG_W,
                     sm + WSIG_OFF + s*STG_W, sm + BIN_OFF + s*HSP,
                     sm + BMU_OFF + s*66, sm + BSIG_OFF + s*66, logdet);
        }
    }

    // epilogue: write z, reduce logpz / logqz across the lane pair
    float sq = 0.f;
    float4* o1 = (float4*)(g_out + rb + q*32);
    float4* o2 = (float4*)(g_out + rb + 64 + q*32);
#pragma unroll
    for (int i = 0; i < 8; i++) {
        float a = z1[4*i+0], b = z1[4*i+1], c = z1[4*i+2], d = z1[4*i+3];
        o1[i] = make_float4(a, b, c, d);
        sq += (a*a + b*b) + (c*c + d*d);
    }
#pragma unroll
    for (int i = 0; i < 8; i++) {
        float a = z2[4*i+0], b = z2[4*i+1], c = z2[4*i+2], d = z2[4*i+3];
        o2[i] = make_float4(a, b, c, d);
        sq += (a*a + b*b) + (c*c + d*d);
    }
    sq     += __shfl_xor_sync(0xffffffffu, sq, 1);
    part   += __shfl_xor_sync(0xffffffffu, part, 1);
    logdet += __shfl_xor_sync(0xffffffffu, logdet, 1);
    if (q == 0) {
        g_out[(size_t)NB*ZDIM + row]      = -0.5f * sq;            // logpz
        g_out[(size_t)NB*ZDIM + NB + row] = -0.5f * part - logdet; // logqz
    }
}

extern "C" void kernel_launch(void* const* d_in, const int* in_sizes, int n_in,
                              void* d_out, int out_size)
{
    (void)in_sizes; (void)n_in; (void)out_size;
    cudaFuncSetAttribute(flow_kernel,
                         cudaFuncAttributeMaxDynamicSharedMemorySize, SMEM_BYTES);
    flow_kernel<<<GRID, NTHREADS, SMEM_BYTES>>>(
        (const float*)d_in[0], (const float*)d_in[1], (const float*)d_in[2],
        (const float*)d_in[3], (const float*)d_in[4], (const float*)d_in[5],
        (const float*)d_in[6], (const float*)d_in[7], (const float*)d_in[8],
        (float*)d_out);
}

// round 8
// speedup vs baseline: 1.5140x; 1.0904x over previous
#include <cuda_runtime.h>

#define NB       262144
#define ZDIM     128
#define ZH       64
#define HS       50
#define HSP      52                      // row stride in floats
#define NSTAGE   4
#define NTHREADS 256                     // 2 lanes/row x 2 rows/thread = 256 rows/CTA
#define GRID     1024                    // NB / 256

#define MBLK     (ZH*HSP + 16)           // 3344 floats: one matrix + guard pad

// SMEM layout (float offsets)
#define W0T_OFF  0                        // [s][k][j] transposed W_in
#define WMU_OFF  (NSTAGE*MBLK)            // [s][o][j]
#define WSIG_OFF (2*NSTAGE*MBLK)
#define BIN_OFF  (3*NSTAGE*MBLK)          // [s][68] (52 + guard)
#define BMU_OFF  (BIN_OFF + NSTAGE*68)    // [s][66]: halves at 33-stride
#define BSIG_OFF (BMU_OFF + NSTAGE*66)
#define ZPARK_OFF (BSIG_OFF + NSTAGE*66)  // [64][NTHREADS]: rows A (0..31), B (32..63)
#define SMEM_FLOATS (ZPARK_OFF + 64*NTHREADS)   // 57312
#define SMEM_BYTES  (SMEM_FLOATS*4)             // 229248

typedef unsigned long long ull;

__device__ __forceinline__ ull pack2(float lo, float hi) {
    ull r; asm("mov.b64 %0,{%1,%2};" : "=l"(r) : "f"(lo), "f"(hi)); return r;
}
__device__ __forceinline__ void unpack2(ull v, float &lo, float &hi) {
    asm("mov.b64 {%0,%1},%2;" : "=f"(lo), "=f"(hi) : "l"(v));
}
__device__ __forceinline__ void fma2(ull &d, ull a, ull b) {
    asm("fma.rn.f32x2 %0,%1,%2,%0;" : "+l"(d) : "l"(a), "l"(b));
}
__device__ __forceinline__ float rcpa(float x) {
    float r; asm("rcp.approx.f32 %0,%1;" : "=f"(r) : "f"(x)); return r;
}
__device__ __forceinline__ float hsum4(ull a, ull b) {
    float x0,x1,x2,x3; unpack2(a,x0,x1); unpack2(b,x2,x3);
    return (x0+x1)+(x2+x3);
}

// Dual-row coupling half-step, lane-pair cooperative with j-split h.
// Lane q owns zin[32] elements k=q*32+kl for rows A,B; h-half j in [q*28, q*28+28);
// updates zout elements o=q*32+i for rows A,B via SMEM park RMW.
__device__ __forceinline__ void coupling_dual(
    const float (&zA)[32], const float (&zB)[32], const int q, const int tid,
    const float* __restrict__ w0t_s, const float* __restrict__ wmu_s,
    const float* __restrict__ wsig_s, const float* __restrict__ bin_s,
    const float* __restrict__ bmu_s,  const float* __restrict__ bsig_s,
    float* __restrict__ park, float &ldA, float &ldB)
{
    ull hA[14], hB[14];
    {   // bias init for own j-half (q=1 slots j>=52 are zeroed guard)
        const ulonglong2* bh = (const ulonglong2*)(bin_s + q*28);
#pragma unroll
        for (int p = 0; p < 7; p++) {
            ulonglong2 b = bh[p];
            hA[2*p] = b.x; hA[2*p+1] = b.y;
            hB[2*p] = b.x; hB[2*p+1] = b.y;
        }
    }
    // phase 1: accumulate own j-half over all 64 k; peer z via packed shfl.
    {
        const float* wb = w0t_s + q*28;
#pragma unroll 2
        for (int i = 0; i < 16; i++) {
            ull mA = pack2(zA[2*i], zA[2*i+1]);
            ull rAx = __shfl_xor_sync(0xffffffffu, mA, 1);
            ull mB = pack2(zB[2*i], zB[2*i+1]);
            ull rBx = __shfl_xor_sync(0xffffffffu, mB, 1);
            float a0,a1,b0,b1,c0,c1,d0,d1;
            unpack2(q ? rAx : mA, a0, a1);   // row A, k = 2i, 2i+1
            unpack2(q ? mA : rAx, b0, b1);   // row A, k = 32+2i, 33+2i
            unpack2(q ? rBx : mB, c0, c1);   // row B low k
            unpack2(q ? mB : rBx, d0, d1);   // row B high k
            const ulonglong2* r0 = (const ulonglong2*)(wb + (2*i    )*HSP);
            const ulonglong2* r1 = (const ulonglong2*)(wb + (2*i + 1)*HSP);
            const ulonglong2* r2 = (const ulonglong2*)(wb + (32+2*i )*HSP);
            const ulonglong2* r3 = (const ulonglong2*)(wb + (33+2*i )*HSP);
            ull zA0=pack2(a0,a0), zA1=pack2(a1,a1), zA2=pack2(b0,b0), zA3=pack2(b1,b1);
            ull zB0=pack2(c0,c0), zB1=pack2(c1,c1), zB2=pack2(d0,d0), zB3=pack2(d1,d1);
#pragma unroll
            for (int p = 0; p < 7; p++) {
                ulonglong2 w0 = r0[p], w1 = r1[p], w2 = r2[p], w3 = r3[p];
                fma2(hA[2*p], zA0, w0.x); fma2(hA[2*p+1], zA0, w0.y);
                fma2(hA[2*p], zA1, w1.x); fma2(hA[2*p+1], zA1, w1.y);
                fma2(hA[2*p], zA2, w2.x); fma2(hA[2*p+1], zA2, w2.y);
                fma2(hA[2*p], zA3, w3.x); fma2(hA[2*p+1], zA3, w3.y);
                fma2(hB[2*p], zB0, w0.x); fma2(hB[2*p+1], zB0, w0.y);
                fma2(hB[2*p], zB1, w1.x); fma2(hB[2*p+1], zB1, w1.y);
                fma2(hB[2*p], zB2, w2.x); fma2(hB[2*p+1], zB2, w2.y);
                fma2(hB[2*p], zB3, w3.x); fma2(hB[2*p+1], zB3, w3.y);
            }
        }
    }
    // tanh own half; zero the q=1 overhang pads (j=52..55 read garbage)
#pragma unroll
    for (int p = 0; p < 14; p++) {
        float x,y; unpack2(hA[p], x, y); hA[p] = pack2(tanhf(x), tanhf(y));
        float u,v; unpack2(hB[p], u, v); hB[p] = pack2(tanhf(u), tanhf(v));
    }
    if (q) { hA[12]=0ull; hA[13]=0ull; hB[12]=0ull; hB[13]=0ull; }

    // phase 2: per output i, half-dots for own (o=q*32+i) and peer output over
    // own j-half; one packed shfl per row merges cross partials; park RMW.
    const float* wmb = wmu_s  + q*28;
    const float* wsb = wsig_s + q*28;
    const float* bm  = bmu_s  + q*33;
    const float* bs  = bsig_s + q*33;
    int own  = (q*32) * HSP;
    int peer = ((1-q)*32) * HSP;
#pragma unroll 4
    for (int i = 0; i < 32; i++) {
        ull aoA0=0,aoA1=0,soA0=0,soA1=0, apA0=0,apA1=0,spA0=0,spA1=0;
        ull aoB0=0,aoB1=0,soB0=0,soB1=0, apB0=0,apB1=0,spB0=0,spB1=0;
        const ulonglong2* wmo = (const ulonglong2*)(wmb + own);
        const ulonglong2* wso = (const ulonglong2*)(wsb + own);
        const ulonglong2* wmp = (const ulonglong2*)(wmb + peer);
        const ulonglong2* wsp = (const ulonglong2*)(wsb + peer);
#pragma unroll
        for (int p = 0; p < 7; p++) {
            ulonglong2 a = wmo[p];
            fma2(aoA0, hA[2*p], a.x); fma2(aoA1, hA[2*p+1], a.y);
            fma2(aoB0, hB[2*p], a.x); fma2(aoB1, hB[2*p+1], a.y);
            ulonglong2 b = wso[p];
            fma2(soA0, hA[2*p], b.x); fma2(soA1, hA[2*p+1], b.y);
            fma2(soB0, hB[2*p], b.x); fma2(soB1, hB[2*p+1], b.y);
            ulonglong2 c = wmp[p];
            fma2(apA0, hA[2*p], c.x); fma2(apA1, hA[2*p+1], c.y);
            fma2(apB0, hB[2*p], c.x); fma2(apB1, hB[2*p+1], c.y);
            ulonglong2 d = wsp[p];
            fma2(spA0, hA[2*p], d.x); fma2(spA1, hA[2*p+1], d.y);
            fma2(spB0, hB[2*p], d.x); fma2(spB1, hB[2*p+1], d.y);
        }
        ull xA = __shfl_xor_sync(0xffffffffu,
                   pack2(hsum4(apA0,apA1), hsum4(spA0,spA1)), 1);
        ull xB = __shfl_xor_sync(0xffffffffu,
                   pack2(hsum4(apB0,apB1), hsum4(spB0,spB1)), 1);
        float rmA, rtA; unpack2(xA, rmA, rtA);
        float rmB, rtB; unpack2(xB, rmB, rtB);
        float bmi = bm[i], bsi = bs[i];
        float muA = bmi + (hsum4(aoA0,aoA1) + rmA);
        float tA  = bsi + (hsum4(soA0,soA1) + rtA);
        float muB = bmi + (hsum4(aoB0,aoB1) + rmB);
        float tB  = bsi + (hsum4(soB0,soB1) + rtB);
        float eA = __expf(-tA), uA = 1.0f + eA, sgA = rcpa(uA);
        float eB = __expf(-tB), uB = 1.0f + eB, sgB = rcpa(uB);
        float* pA = park + i*NTHREADS + tid;
        float* pB = park + (32+i)*NTHREADS + tid;
        *pA = (*pA)*sgA + muA;
        *pB = (*pB)*sgB + muB;
        ldA -= __logf(uA);                 // log(sigmoid(t)) = -log(1+e^-t)
        ldB -= __logf(uB);
        own  += HSP;
        peer += HSP;
    }
}

__global__ void __launch_bounds__(NTHREADS, 1) flow_kernel(
    const float* __restrict__ g_mean, const float* __restrict__ g_logvar,
    const float* __restrict__ g_eps,
    const float* __restrict__ g_Win,  const float* __restrict__ g_bin,
    const float* __restrict__ g_Wmu,  const float* __restrict__ g_bmu,
    const float* __restrict__ g_Wsig, const float* __restrict__ g_bsig,
    float* __restrict__ g_out)
{
    extern __shared__ float sm[];
    const int tid = threadIdx.x;

    // zero weight region (covers pads/guards), then stage weights
    for (int i = tid; i < ZPARK_OFF; i += NTHREADS) sm[i] = 0.f;
    __syncthreads();
    for (int i = tid; i < NSTAGE*HS*ZH; i += NTHREADS) {   // W_in -> [s][k][j]
        int s = i / (HS*ZH); int r = i - s*(HS*ZH);
        int j = r / ZH;      int k = r - j*ZH;
        sm[W0T_OFF + s*MBLK + k*HSP + j] = g_Win[i];
    }
    for (int i = tid; i < NSTAGE*ZH*HS; i += NTHREADS) {   // W_mu/W_sig -> [s][o][j]
        int s = i / (ZH*HS); int r = i - s*(ZH*HS);
        int o = r / HS;      int j = r - o*HS;
        int off = s*MBLK + o*HSP + j;
        sm[WMU_OFF  + off] = g_Wmu[i];
        sm[WSIG_OFF + off] = g_Wsig[i];
    }
    for (int i = tid; i < NSTAGE*HS; i += NTHREADS) {
        int s = i / HS; int j = i - s*HS;
        sm[BIN_OFF + s*68 + j] = g_bin[i];
    }
    for (int i = tid; i < NSTAGE*ZH; i += NTHREADS) {
        int s = i / ZH; int o = i - s*ZH;
        int oo = o + (o >> 5);                              // halves at 33-stride
        sm[BMU_OFF  + s*66 + oo] = g_bmu[i];
        sm[BSIG_OFF + s*66 + oo] = g_bsig[i];
    }
    __syncthreads();

    const int p = tid >> 1;
    const int q = tid & 1;
    const size_t rA = (size_t)blockIdx.x * 256 + p;          // rows 0..127 of tile
    const size_t rB = rA + 128;                              // rows 128..255
    float* park = sm + ZPARK_OFF;

    // z1 halves -> registers; z2 halves -> park; accumulate -2*logqz0 partials
    float zA[32], zB[32];
    float partA = 0.f, partB = 0.f;
    {
        const float4* m4 = (const float4*)(g_mean   + rA*ZDIM + q*32);
        const float4* l4 = (const float4*)(g_logvar + rA*ZDIM + q*32);
        const float4* e4 = (const float4*)(g_eps    + rA*ZDIM + q*32);
#pragma unroll
        for (int i = 0; i < 8; i++) {
            float4 m = m4[i], l = l4[i], e = e4[i];
            zA[4*i+0] = e.x * __expf(0.5f*l.x) + m.x;
            zA[4*i+1] = e.y * __expf(0.5f*l.y) + m.y;
            zA[4*i+2] = e.z * __expf(0.5f*l.z) + m.z;
            zA[4*i+3] = e.w * __expf(0.5f*l.w) + m.w;
            partA += (l.x + l.y) + (l.z + l.w)
                   + (e.x*e.x + e.y*e.y) + (e.z*e.z + e.w*e.w);
        }
    }
    {
        const float4* m4 = (const float4*)(g_mean   + rB*ZDIM + q*32);
        const float4* l4 = (const float4*)(g_logvar + rB*ZDIM + q*32);
        const float4* e4 = (const float4*)(g_eps    + rB*ZDIM + q*32);
#pragma unroll
        for (int i = 0; i < 8; i++) {
            float4 m = m4[i], l = l4[i], e = e4[i];
            zB[4*i+0] = e.x * __expf(0.5f*l.x) + m.x;
            zB[4*i+1] = e.y * __expf(0.5f*l.y) + m.y;
            zB[4*i+2] = e.z * __expf(0.5f*l.z) + m.z;
            zB[4*i+3] = e.w * __expf(0.5f*l.w) + m.w;
            partB += (l.x + l.y) + (l.z + l.w)
                   + (e.x*e.x + e.y*e.y) + (e.z*e.z + e.w*e.w);
        }
    }
    {
        const float4* m4 = (const float4*)(g_mean   + rA*ZDIM + 64 + q*32);
        const float4* l4 = (const float4*)(g_logvar + rA*ZDIM + 64 + q*32);
        const float4* e4 = (const float4*)(g_eps    + rA*ZDIM + 64 + q*32);
#pragma unroll
        for (int i = 0; i < 8; i++) {
            float4 m = m4[i], l = l4[i], e = e4[i];
            park[(4*i+0)*NTHREADS + tid] = e.x * __expf(0.5f*l.x) + m.x;
            park[(4*i+1)*NTHREADS + tid] = e.y * __expf(0.5f*l.y) + m.y;
            park[(4*i+2)*NTHREADS + tid] = e.z * __expf(0.5f*l.z) + m.z;
            park[(4*i+3)*NTHREADS + tid] = e.w * __expf(0.5f*l.w) + m.w;
            partA += (l.x + l.y) + (l.z + l.w)
                   + (e.x*e.x + e.y*e.y) + (e.z*e.z + e.w*e.w);
        }
    }
    {
        const float4* m4 = (const float4*)(g_mean   + rB*ZDIM + 64 + q*32);
        const float4* l4 = (const float4*)(g_logvar + rB*ZDIM + 64 + q*32);
        const float4* e4 = (const float4*)(g_eps    + rB*ZDIM + 64 + q*32);
#pragma unroll
        for (int i = 0; i < 8; i++) {
            float4 m = m4[i], l = l4[i], e = e4[i];
            park[(32+4*i+0)*NTHREADS + tid] = e.x * __expf(0.5f*l.x) + m.x;
            park[(32+4*i+1)*NTHREADS + tid] = e.y * __expf(0.5f*l.y) + m.y;
            park[(32+4*i+2)*NTHREADS + tid] = e.z * __expf(0.5f*l.z) + m.z;
            park[(32+4*i+3)*NTHREADS + tid] = e.w * __expf(0.5f*l.w) + m.w;
            partB += (l.x + l.y) + (l.z + l.w)
                   + (e.x*e.x + e.y*e.y) + (e.z*e.z + e.w*e.w);
        }
    }

    float ldA = 0.f, ldB = 0.f;
#pragma unroll 1     // keep flow loop rolled: bounds I-cache footprint
    for (int f = 0; f < 2; f++) {
        const int s0 = 2*f, s1 = 2*f + 1;
        // coupling(z1 -> z2): zin = regs (z1), zout = park (z2)
        coupling_dual(zA, zB, q, tid,
                      sm + W0T_OFF + s0*MBLK, sm + WMU_OFF + s0*MBLK,
                      sm + WSIG_OFF + s0*MBLK, sm + BIN_OFF + s0*68,
                      sm + BMU_OFF + s0*66, sm + BSIG_OFF + s0*66,
                      park, ldA, ldB);
        // swap: regs <-> park  (regs become z2, park becomes z1)
#pragma unroll
        for (int i = 0; i < 32; i++) {
            float tA_ = park[i*NTHREADS + tid];
            park[i*NTHREADS + tid] = zA[i];  zA[i] = tA_;
            float tB_ = park[(32+i)*NTHREADS + tid];
            park[(32+i)*NTHREADS + tid] = zB[i];  zB[i] = tB_;
        }
        // coupling(z2 -> z1)
        coupling_dual(zA, zB, q, tid,
                      sm + W0T_OFF + s1*MBLK, sm + WMU_OFF + s1*MBLK,
                      sm + WSIG_OFF + s1*MBLK, sm + BIN_OFF + s1*68,
                      sm + BMU_OFF + s1*66, sm + BSIG_OFF + s1*66,
                      park, ldA, ldB);
        // swap back: regs become z1, park becomes z2
#pragma unroll
        for (int i = 0; i < 32; i++) {
            float tA_ = park[i*NTHREADS + tid];
            park[i*NTHREADS + tid] = zA[i];  zA[i] = tA_;
            float tB_ = park[(32+i)*NTHREADS + tid];
            park[(32+i)*NTHREADS + tid] = zB[i];  zB[i] = tB_;
        }
    }

    // epilogue: z1 in regs, z2 in park
    float sqA = 0.f, sqB = 0.f;
    {
        float4* oA = (float4*)(g_out + rA*ZDIM + q*32);
        float4* oB = (float4*)(g_out + rB*ZDIM + q*32);
#pragma unroll
        for (int i = 0; i < 8; i++) {
            float a = zA[4*i+0], b = zA[4*i+1], c = zA[4*i+2], d = zA[4*i+3];
            oA[i] = make_float4(a, b, c, d);
            sqA += (a*a + b*b) + (c*c + d*d);
            float e = zB[4*i+0], fv = zB[4*i+1], g = zB[4*i+2], h = zB[4*i+3];
            oB[i] = make_float4(e, fv, g, h);
            sqB += (e*e + fv*fv) + (g*g + h*h);
        }
    }
    {
        float4* oA = (float4*)(g_out + rA*ZDIM + 64 + q*32);
        float4* oB = (float4*)(g_out + rB*ZDIM + 64 + q*32);
#pragma unroll
        for (int i = 0; i < 8; i++) {
            float a = park[(4*i+0)*NTHREADS + tid];
            float b = park[(4*i+1)*NTHREADS + tid];
            float c = park[(4*i+2)*NTHREADS + tid];
            float d = park[(4*i+3)*NTHREADS + tid];
            oA[i] = make_float4(a, b, c, d);
            sqA += (a*a + b*b) + (c*c + d*d);
            float e = park[(32+4*i+0)*NTHREADS + tid];
            float fv= park[(32+4*i+1)*NTHREADS + tid];
            float g = park[(32+4*i+2)*NTHREADS + tid];
            float h = park[(32+4*i+3)*NTHREADS + tid];
            oB[i] = make_float4(e, fv, g, h);
            sqB += (e*e + fv*fv) + (g*g + h*h);
        }
    }
    sqA   += __shfl_xor_sync(0xffffffffu, sqA, 1);
    sqB   += __shfl_xor_sync(0xffffffffu, sqB, 1);
    partA += __shfl_xor_sync(0xffffffffu, partA, 1);
    partB += __shfl_xor_sync(0xffffffffu, partB, 1);
    ldA   += __shfl_xor_sync(0xffffffffu, ldA, 1);
    ldB   += __shfl_xor_sync(0xffffffffu, ldB, 1);
    if (q == 0) {
        g_out[(size_t)NB*ZDIM + rA]      = -0.5f * sqA;            // logpz
        g_out[(size_t)NB*ZDIM + NB + rA] = -0.5f * partA - ldA;    // logqz
        g_out[(size_t)NB*ZDIM + rB]      = -0.5f * sqB;
        g_out[(size_t)NB*ZDIM + NB + rB] = -0.5f * partB - ldB;
    }
}

extern "C" void kernel_launch(void* const* d_in, const int* in_sizes, int n_in,
                              void* d_out, int out_size)
{
    (void)in_sizes; (void)n_in; (void)out_size;
    cudaFuncSetAttribute(flow_kernel,
                         cudaFuncAttributeMaxDynamicSharedMemorySize, SMEM_BYTES);
    flow_kernel<<<GRID, NTHREADS, SMEM_BYTES>>>(
        (const float*)d_in[0], (const float*)d_in[1], (const float*)d_in[2],
        (const float*)d_in[3], (const float*)d_in[4], (const float*)d_in[5],
        (const float*)d_in[6], (const float*)d_in[7], (const float*)d_in[8],
        (float*)d_out);
}

// round 11
// speedup vs baseline: 2.0227x; 1.3360x over previous
#include <cuda_runtime.h>
#include <cuda_bf16.h>
#include <cstdint>

#define NB    262144
#define NT    256            // 8 warps x 16 rows = 128 rows/CTA
#define GRID  2048

// SMEM byte offsets. Weight rows are 256B: 16 chunks of 16B; chunks 0-7 = hi
// bf16 (k 0-63), chunks 8-15 = lo bf16. Chunk index XOR-swizzled by (row&7).
#define W0_OFF   0           // 4 stages x 56 rows x 256B  (W_in as [n=j][k])
#define W12_OFF  57344       // 4 x 128 rows x 256B  (rows 0-63 W_mu, 64-127 W_sig)
#define A_OFF    188416      // 8 warps x 16 rows x 256B activation staging
#define BIN_OFF  221184      // f32 [4][64]
#define BMU_OFF  222208      // f32 [4][64]
#define BSIG_OFF 223232      // f32 [4][64]
#define SMEM_TOTAL 224256

__device__ __forceinline__ uint32_t smem_u32(const void* p) {
    uint32_t a;
    asm("{ .reg .u64 t; cvta.to.shared.u64 t, %1; cvt.u32.u64 %0, t; }" : "=r"(a) : "l"(p));
    return a;
}
__device__ __forceinline__ float rcpa(float x) {
    float r; asm("rcp.approx.f32 %0,%1;" : "=f"(r) : "f"(x)); return r;
}
__device__ __forceinline__ float tanh_fast(float x) {   // 2*sigmoid(2x)-1
    float e = __expf(-2.0f * x);
    return __fmaf_rn(2.0f, rcpa(1.0f + e), -1.0f);
}

__device__ __forceinline__ void mma16816(float* d, const uint32_t* a, const uint32_t* b) {
    asm volatile("mma.sync.aligned.m16n8k16.row.col.f32.bf16.bf16.f32 "
        "{%0,%1,%2,%3}, {%4,%5,%6,%7}, {%8,%9}, {%0,%1,%2,%3};"
        : "+f"(d[0]), "+f"(d[1]), "+f"(d[2]), "+f"(d[3])
        : "r"(a[0]), "r"(a[1]), "r"(a[2]), "r"(a[3]), "r"(b[0]), "r"(b[1]));
}
__device__ __forceinline__ void ldm_x4(uint32_t* r, uint32_t a) {
    asm volatile("ldmatrix.sync.aligned.m8n8.x4.shared.b16 {%0,%1,%2,%3}, [%4];"
        : "=r"(r[0]), "=r"(r[1]), "=r"(r[2]), "=r"(r[3]) : "r"(a));
}
__device__ __forceinline__ void ldm_x2(uint32_t* r, uint32_t a) {
    asm volatile("ldmatrix.sync.aligned.m8n8.x2.shared.b16 {%0,%1}, [%2];"
        : "=r"(r[0]), "=r"(r[1]) : "r"(a));
}

// A-fragment ldmatrix address: 16 rows x k-chunk pair (c0, c0+1)
__device__ __forceinline__ uint32_t a_addr(uint32_t base, int lane, int c0) {
    int row = lane & 15;
    int ch  = c0 + (lane >> 4);
    return base + row*256 + ((ch ^ (row & 7)) << 4);
}
// B x4: two 8-row n-tiles (n0, n0+8) x chunk pair (c0, c0+1)
__device__ __forceinline__ uint32_t b_addr4(uint32_t base, int lane, int n0, int c0) {
    int row = n0 + (lane & 7) + ((lane >> 4) << 3);
    int ch  = c0 + ((lane >> 3) & 1);
    return base + row*256 + ((ch ^ (row & 7)) << 4);
}
// B x2: one 8-row n-tile
__device__ __forceinline__ uint32_t b_addr2(uint32_t base, int lane, int n0, int c0) {
    int row = n0 + (lane & 7);
    int ch  = c0 + ((lane >> 3) & 1);
    return base + row*256 + ((ch ^ (row & 7)) << 4);
}

// store (v0,v1) as bf16x2 hi at addr_hi and bf16x2 residual-lo at addr_lo
__device__ __forceinline__ void stage_pair(uint32_t addr_hi, uint32_t addr_lo,
                                           float v0, float v1) {
    uint32_t h;
    asm("cvt.rn.bf16x2.f32 %0, %1, %2;" : "=r"(h) : "f"(v1), "f"(v0)); // low=v0
    asm volatile("st.shared.b32 [%0], %1;" :: "r"(addr_hi), "r"(h));
    float h0 = __uint_as_float(h << 16);
    float h1 = __uint_as_float(h & 0xffff0000u);
    uint32_t l;
    asm("cvt.rn.bf16x2.f32 %0, %1, %2;" : "=r"(l) : "f"(v1 - h1), "f"(v0 - h0));
    asm volatile("st.shared.b32 [%0], %1;" :: "r"(addr_lo), "r"(l));
}

// weight element -> hi/lo bf16 at swizzled [row][k] position
__device__ __forceinline__ void store_w(char* smem, int base, int row, int k, float v) {
    __nv_bfloat16 hb = __float2bfloat16(v);
    __nv_bfloat16 lb = __float2bfloat16(v - __bfloat162float(hb));
    int c = k >> 3, b = (k & 7) * 2;
    *(__nv_bfloat16*)(smem + base + row*256 + (((c    ) ^ (row & 7)) << 4) + b) = hb;
    *(__nv_bfloat16*)(smem + base + row*256 + (((8 + c) ^ (row & 7)) << 4) + b) = lb;
}

__device__ __forceinline__ void tanh_stage(const float* d, int j, const float* bin_s,
                                           uint32_t Abase, int g, int t) {
    float b0 = bin_s[8*j + 2*t], b1 = bin_s[8*j + 2*t + 1];
    float v0 = tanh_fast(d[0] + b0), v1 = tanh_fast(d[1] + b1);
    float v2 = tanh_fast(d[2] + b0), v3 = tanh_fast(d[3] + b1);
    {
        int row = g; uint32_t base = Abase + row*256 + 4*t;
        stage_pair(base + ((j ^ (row&7)) << 4), base + (((8+j) ^ (row&7)) << 4), v0, v1);
    }
    {
        int row = g + 8; uint32_t base = Abase + row*256 + 4*t;
        stage_pair(base + ((j ^ (row&7)) << 4), base + (((8+j) ^ (row&7)) << 4), v2, v3);
    }
}

__device__ __forceinline__ void sig_update(float* zo, const float* dm, const float* ds,
                                           int j, const float* bmu_s, const float* bsig_s,
                                           int t, float& ldA, float& ldB) {
    float bm0 = bmu_s[8*j + 2*t],  bm1 = bmu_s[8*j + 2*t + 1];
    float bs0 = bsig_s[8*j + 2*t], bs1 = bsig_s[8*j + 2*t + 1];
    float t0 = ds[0] + bs0, t1 = ds[1] + bs1, t2 = ds[2] + bs0, t3 = ds[3] + bs1;
    float e0 = __expf(-t0), e1 = __expf(-t1), e2 = __expf(-t2), e3 = __expf(-t3);
    float u0 = 1.f + e0, u1 = 1.f + e1, u2 = 1.f + e2, u3 = 1.f + e3;
    zo[0] = zo[0] * rcpa(u0) + (dm[0] + bm0);
    zo[1] = zo[1] * rcpa(u1) + (dm[1] + bm1);
    zo[2] = zo[2] * rcpa(u2) + (dm[2] + bm0);
    zo[3] = zo[3] * rcpa(u3) + (dm[3] + bm1);
    ldA -= __logf(u0) + __logf(u1);          // rows g / g+8 split
    ldB -= __logf(u2) + __logf(u3);
}

// One coupling half-step: zout = zout*sigmoid(W2 h + b2) + (W1 h + b1),
// h = tanh(W0 zin + b0). zin/zout are D-layout frags [jfrag][4].
__device__ __forceinline__ void coupling(
    float (&zin)[8][4], float (&zout)[8][4], int s,
    uint32_t sb, char* smem, uint32_t Abase,
    int lane, float& ldA, float& ldB)
{
    const int g = lane >> 2, t = lane & 3;
    const uint32_t W0s  = sb + W0_OFF  + s*14336;
    const uint32_t W12s = sb + W12_OFF + s*32768;
    const float* bin_s  = (const float*)(smem + BIN_OFF)  + s*64;
    const float* bmu_s  = (const float*)(smem + BMU_OFF)  + s*64;
    const float* bsig_s = (const float*)(smem + BSIG_OFF) + s*64;

    // stage zin hi/lo into warp-private A buffer
#pragma unroll
    for (int j = 0; j < 8; j++) {
#pragma unroll
        for (int rh = 0; rh < 2; rh++) {
            int row = g + rh*8;
            uint32_t base = Abase + row*256 + 4*t;
            stage_pair(base + ((j ^ (row&7)) << 4), base + (((8+j) ^ (row&7)) << 4),
                       zin[j][rh*2], zin[j][rh*2 + 1]);
        }
    }
    __syncwarp();

    uint32_t aH[4][4], aL[4][4];
#pragma unroll
    for (int kc = 0; kc < 4; kc++) {
        ldm_x4(aH[kc], a_addr(Abase, lane, 2*kc));
        ldm_x4(aL[kc], a_addr(Abase, lane, 8 + 2*kc));
    }
    __syncwarp();   // all reads done before H overwrites the buffer

    // GEMM1: D1 = Z @ W0^T  (n-tiles 0..6), tanh+bias, restage as H
#pragma unroll
    for (int p = 0; p < 3; p++) {
        float d0[4] = {0,0,0,0}, d1[4] = {0,0,0,0};
#pragma unroll
        for (int kc = 0; kc < 4; kc++) {
            uint32_t bh[4], bl[4];
            ldm_x4(bh, b_addr4(W0s, lane, 16*p, 2*kc));
            mma16816(d0, aH[kc], bh);     mma16816(d1, aH[kc], bh + 2);
            mma16816(d0, aL[kc], bh);     mma16816(d1, aL[kc], bh + 2);
            ldm_x4(bl, b_addr4(W0s, lane, 16*p, 8 + 2*kc));
            mma16816(d0, aH[kc], bl);     mma16816(d1, aH[kc], bl + 2);
        }
        tanh_stage(d0, 2*p,     bin_s, Abase, g, t);
        tanh_stage(d1, 2*p + 1, bin_s, Abase, g, t);
    }
    {   // n-tile 6 (cols 48-55; 50-55 zero via zero W0 rows + zero bias)
        float d6[4] = {0,0,0,0};
#pragma unroll
        for (int kc = 0; kc < 4; kc++) {
            uint32_t bh[2], bl[2];
            ldm_x2(bh, b_addr2(W0s, lane, 48, 2*kc));
            mma16816(d6, aH[kc], bh);
            mma16816(d6, aL[kc], bh);
            ldm_x2(bl, b_addr2(W0s, lane, 48, 8 + 2*kc));
            mma16816(d6, aH[kc], bl);
        }
        tanh_stage(d6, 6, bin_s, Abase, g, t);
        // zero-fill H cols 56-63 (hi chunk 7, lo chunk 15)
#pragma unroll
        for (int rh = 0; rh < 2; rh++) {
            int row = g + rh*8;
            uint32_t base = Abase + row*256 + 4*t;
            asm volatile("st.shared.b32 [%0], %1;"
                         :: "r"(base + ((7  ^ (row&7)) << 4)), "r"(0u));
            asm volatile("st.shared.b32 [%0], %1;"
                         :: "r"(base + ((15 ^ (row&7)) << 4)), "r"(0u));
        }
    }
    __syncwarp();

    // reload A frags as H
#pragma unroll
    for (int kc = 0; kc < 4; kc++) {
        ldm_x4(aH[kc], a_addr(Abase, lane, 2*kc));
        ldm_x4(aL[kc], a_addr(Abase, lane, 8 + 2*kc));
    }

    // GEMM2: [MU|SIG] = H @ [W_mu;W_sig]^T; groups of 2 output tiles
#pragma unroll
    for (int p = 0; p < 4; p++) {
        float dm0[4]={0,0,0,0}, dm1[4]={0,0,0,0}, ds0[4]={0,0,0,0}, ds1[4]={0,0,0,0};
#pragma unroll
        for (int kc = 0; kc < 4; kc++) {
            uint32_t bmh[4], bsh[4], bml[4], bsl[4];
            ldm_x4(bmh, b_addr4(W12s, lane, 16*p,      2*kc));
            ldm_x4(bsh, b_addr4(W12s, lane, 64 + 16*p, 2*kc));
            mma16816(dm0, aH[kc], bmh);   mma16816(dm1, aH[kc], bmh + 2);
            mma16816(ds0, aH[kc], bsh);   mma16816(ds1, aH[kc], bsh + 2);
            mma16816(dm0, aL[kc], bmh);   mma16816(dm1, aL[kc], bmh + 2);
            mma16816(ds0, aL[kc], bsh);   mma16816(ds1, aL[kc], bsh + 2);
            ldm_x4(bml, b_addr4(W12s, lane, 16*p,      8 + 2*kc));
            ldm_x4(bsl, b_addr4(W12s, lane, 64 + 16*p, 8 + 2*kc));
            mma16816(dm0, aH[kc], bml);   mma16816(dm1, aH[kc], bml + 2);
            mma16816(ds0, aH[kc], bsl);   mma16816(ds1, aH[kc], bsl + 2);
        }
        sig_update(zout[2*p],     dm0, ds0, 2*p,     bmu_s, bsig_s, t, ldA, ldB);
        sig_update(zout[2*p + 1], dm1, ds1, 2*p + 1, bmu_s, bsig_s, t, ldA, ldB);
    }
}

__global__ void __launch_bounds__(NT, 1) flow_kernel(
    const float* __restrict__ g_mean, const float* __restrict__ g_logvar,
    const float* __restrict__ g_eps,
    const float* __restrict__ g_Win,  const float* __restrict__ g_bin,
    const float* __restrict__ g_Wmu,  const float* __restrict__ g_bmu,
    const float* __restrict__ g_Wsig, const float* __restrict__ g_bsig,
    float* __restrict__ g_out)
{
    extern __shared__ char smem[];
    const uint32_t sb = smem_u32(smem);
    const int tid  = threadIdx.x;
    const int warp = tid >> 5, lane = tid & 31;
    const int g = lane >> 2, t = lane & 3;

    // zero whole SMEM (covers all pads), then stage weights hi/lo + biases
    for (int i = tid; i < SMEM_TOTAL/4; i += NT) ((uint32_t*)smem)[i] = 0u;
    __syncthreads();
    for (int i = tid; i < 4*50*64; i += NT) {                 // W_in [s][j][k]
        int s = i / 3200, r = i - s*3200, j = r >> 6, k = r & 63;
        store_w(smem, W0_OFF + s*14336, j, k, g_Win[i]);
    }
    for (int i = tid; i < 4*128*50; i += NT) {                // W_mu / W_sig rows
        int s = i / 6400, r = i - s*6400, o = r / 50, k = r - o*50;
        float v = (o < 64) ? g_Wmu[s*3200 + o*50 + k] : g_Wsig[s*3200 + (o-64)*50 + k];
        store_w(smem, W12_OFF + s*32768, o, k, v);
    }
    for (int i = tid; i < 200; i += NT) {
        int s = i / 50, j = i - s*50;
        ((float*)(smem + BIN_OFF))[s*64 + j] = g_bin[i];
    }
    for (int i = tid; i < 256; i += NT) {
        ((float*)(smem + BMU_OFF))[i]  = g_bmu[i];
        ((float*)(smem + BSIG_OFF))[i] = g_bsig[i];
    }
    __syncthreads();

    const uint32_t Abase = sb + A_OFF + warp*4096;
    const size_t rowA = (size_t)blockIdx.x*128 + warp*16 + g;
    const size_t rowB = rowA + 8;

    // prologue: z frags (D layout) + logqz0 partials per row-half
    float z1[8][4], z2[8][4];
    float partA = 0.f, partB = 0.f;
#pragma unroll
    for (int j = 0; j < 8; j++) {
        int c1 = 8*j + 2*t, c2 = 64 + c1;
        float2 m, l, e;
        m = *(const float2*)(g_mean + rowA*128 + c1);
        l = *(const float2*)(g_logvar + rowA*128 + c1);
        e = *(const float2*)(g_eps + rowA*128 + c1);
        z1[j][0] = e.x*__expf(0.5f*l.x) + m.x;  z1[j][1] = e.y*__expf(0.5f*l.y) + m.y;
        partA += l.x + l.y + e.x*e.x + e.y*e.y;
        m = *(const float2*)(g_mean + rowB*128 + c1);
        l = *(const float2*)(g_logvar + rowB*128 + c1);
        e = *(const float2*)(g_eps + rowB*128 + c1);
        z1[j][2] = e.x*__expf(0.5f*l.x) + m.x;  z1[j][3] = e.y*__expf(0.5f*l.y) + m.y;
        partB += l.x + l.y + e.x*e.x + e.y*e.y;
        m = *(const float2*)(g_mean + rowA*128 + c2);
        l = *(const float2*)(g_logvar + rowA*128 + c2);
        e = *(const float2*)(g_eps + rowA*128 + c2);
        z2[j][0] = e.x*__expf(0.5f*l.x) + m.x;  z2[j][1] = e.y*__expf(0.5f*l.y) + m.y;
        partA += l.x + l.y + e.x*e.x + e.y*e.y;
        m = *(const float2*)(g_mean + rowB*128 + c2);
        l = *(const float2*)(g_logvar + rowB*128 + c2);
        e = *(const float2*)(g_eps + rowB*128 + c2);
        z2[j][2] = e.x*__expf(0.5f*l.x) + m.x;  z2[j][3] = e.y*__expf(0.5f*l.y) + m.y;
        partB += l.x + l.y + e.x*e.x + e.y*e.y;
    }

    float ldA = 0.f, ldB = 0.f;
#pragma unroll 1   // rolled: bounds I-cache to 2 coupling bodies
    for (int f = 0; f < 2; f++) {
        coupling(z1, z2, 2*f,     sb, smem, Abase, lane, ldA, ldB);
        coupling(z2, z1, 2*f + 1, sb, smem, Abase, lane, ldA, ldB);
    }

    // epilogue: write z, reduce logpz/logqz across the quad (lanes sharing g)
    float sqA = 0.f, sqB = 0.f;
#pragma unroll
    for (int j = 0; j < 8; j++) {
        int c1 = 8*j + 2*t, c2 = 64 + c1;
        *(float2*)(g_out + rowA*128 + c1) = make_float2(z1[j][0], z1[j][1]);
        *(float2*)(g_out + rowB*128 + c1) = make_float2(z1[j][2], z1[j][3]);
        *(float2*)(g_out + rowA*128 + c2) = make_float2(z2[j][0], z2[j][1]);
        *(float2*)(g_out + rowB*128 + c2) = make_float2(z2[j][2], z2[j][3]);
        sqA += z1[j][0]*z1[j][0] + z1[j][1]*z1[j][1]
             + z2[j][0]*z2[j][0] + z2[j][1]*z2[j][1];
        sqB += z1[j][2]*z1[j][2] + z1[j][3]*z1[j][3]
             + z2[j][2]*z2[j][2] + z2[j][3]*z2[j][3];
    }
#pragma unroll
    for (int d = 1; d <= 2; d <<= 1) {
        sqA   += __shfl_xor_sync(0xffffffffu, sqA, d);
        sqB   += __shfl_xor_sync(0xffffffffu, sqB, d);
        partA += __shfl_xor_sync(0xffffffffu, partA, d);
        partB += __shfl_xor_sync(0xffffffffu, partB, d);
        ldA   += __shfl_xor_sync(0xffffffffu, ldA, d);
        ldB   += __shfl_xor_sync(0xffffffffu, ldB, d);
    }
    if (t == 0) {
        g_out[(size_t)NB*128 + rowA]      = -0.5f * sqA;
        g_out[(size_t)NB*128 + NB + rowA] = -0.5f * partA - ldA;
        g_out[(size_t)NB*128 + rowB]      = -0.5f * sqB;
        g_out[(size_t)NB*128 + NB + rowB] = -0.5f * partB - ldB;
    }
}

extern "C" void kernel_launch(void* const* d_in, const int* in_sizes, int n_in,
                              void* d_out, int out_size)
{
    (void)in_sizes; (void)n_in; (void)out_size;
    cudaFuncSetAttribute(flow_kernel,
                         cudaFuncAttributeMaxDynamicSharedMemorySize, SMEM_TOTAL);
    flow_kernel<<<GRID, NT, SMEM_TOTAL>>>(
        (const float*)d_in[0], (const float*)d_in[1], (const float*)d_in[2],
        (const float*)d_in[3], (const float*)d_in[4], (const float*)d_in[5],
        (const float*)d_in[6], (const float*)d_in[7], (const float*)d_in[8],
        (float*)d_out);
}

// round 12
// speedup vs baseline: 2.3158x; 1.1449x over previous
#include <cuda_runtime.h>
#include <cuda_bf16.h>
#include <cstdint>

#define NB    262144
#define NT    256            // 8 warps x 16 rows = 128 rows/CTA
#define GRID  2048

// SMEM byte offsets. Weight rows are 256B: 16 chunks of 16B; chunks 0-7 = hi
// bf16 (k 0-63), chunks 8-15 = lo bf16. Chunk index XOR-swizzled by (row&7).
#define W0_OFF   0           // 4 stages x 56 rows x 256B  (W_in as [n=j][k])
#define W12_OFF  57344       // 4 x 128 rows x 256B (rows 0-63 W_mu, 64-127 W_sig)
#define BIN_OFF  188416      // f32 [4][64]
#define BMU_OFF  189440      // f32 [4][64]
#define BSIG_OFF 190464      // f32 [4][64]
#define SMEM_TOTAL 191488

__device__ __forceinline__ uint32_t smem_u32(const void* p) {
    uint32_t a;
    asm("{ .reg .u64 t; cvta.to.shared.u64 t, %1; cvt.u32.u64 %0, t; }" : "=r"(a) : "l"(p));
    return a;
}
__device__ __forceinline__ float rcpa(float x) {
    float r; asm("rcp.approx.f32 %0,%1;" : "=f"(r) : "f"(x)); return r;
}
__device__ __forceinline__ float tanh_fast(float x) {   // 2*sigmoid(2x)-1
    float e = __expf(-2.0f * x);
    return __fmaf_rn(2.0f, rcpa(1.0f + e), -1.0f);
}

__device__ __forceinline__ void mma16816(float* d, const uint32_t* a, const uint32_t* b) {
    asm volatile("mma.sync.aligned.m16n8k16.row.col.f32.bf16.bf16.f32 "
        "{%0,%1,%2,%3}, {%4,%5,%6,%7}, {%8,%9}, {%0,%1,%2,%3};"
        : "+f"(d[0]), "+f"(d[1]), "+f"(d[2]), "+f"(d[3])
        : "r"(a[0]), "r"(a[1]), "r"(a[2]), "r"(a[3]), "r"(b[0]), "r"(b[1]));
}
__device__ __forceinline__ void ldm_x4(uint32_t* r, uint32_t a) {
    asm volatile("ldmatrix.sync.aligned.m8n8.x4.shared.b16 {%0,%1,%2,%3}, [%4];"
        : "=r"(r[0]), "=r"(r[1]), "=r"(r[2]), "=r"(r[3]) : "r"(a));
}
__device__ __forceinline__ void ldm_x2(uint32_t* r, uint32_t a) {
    asm volatile("ldmatrix.sync.aligned.m8n8.x2.shared.b16 {%0,%1}, [%2];"
        : "=r"(r[0]), "=r"(r[1]) : "r"(a));
}

// B x4: two 8-row n-tiles (n0, n0+8) x chunk pair (c0, c0+1)
__device__ __forceinline__ uint32_t b_addr4(uint32_t base, int lane, int n0, int c0) {
    int row = n0 + (lane & 7) + ((lane >> 4) << 3);
    int ch  = c0 + ((lane >> 3) & 1);
    return base + row*256 + ((ch ^ (row & 7)) << 4);
}
// B x2: one 8-row n-tile
__device__ __forceinline__ uint32_t b_addr2(uint32_t base, int lane, int n0, int c0) {
    int row = n0 + (lane & 7);
    int ch  = c0 + ((lane >> 3) & 1);
    return base + row*256 + ((ch ^ (row & 7)) << 4);
}

// pack (x,y) into hi-bf16x2 h and residual-lo-bf16x2 l (low half = x)
__device__ __forceinline__ void packhl(float x, float y, uint32_t &h, uint32_t &l) {
    asm("cvt.rn.bf16x2.f32 %0, %1, %2;" : "=r"(h) : "f"(y), "f"(x));
    float h0 = __uint_as_float(h << 16);
    float h1 = __uint_as_float(h & 0xffff0000u);
    asm("cvt.rn.bf16x2.f32 %0, %1, %2;" : "=r"(l) : "f"(y - h1), "f"(x - h0));
}

// weight element -> hi/lo bf16 at swizzled [row][k] position
__device__ __forceinline__ void store_w(char* smem, int base, int row, int k, float v) {
    __nv_bfloat16 hb = __float2bfloat16(v);
    __nv_bfloat16 lb = __float2bfloat16(v - __bfloat162float(hb));
    int c = k >> 3, b = (k & 7) * 2;
    *(__nv_bfloat16*)(smem + base + row*256 + (((c    ) ^ (row & 7)) << 4) + b) = hb;
    *(__nv_bfloat16*)(smem + base + row*256 + (((8 + c) ^ (row & 7)) << 4) + b) = lb;
}

__device__ __forceinline__ void sig_update(float* zo, const float* dm, const float* ds,
                                           int j, const float* bmu_s, const float* bsig_s,
                                           int t, float& ldA, float& ldB) {
    float bm0 = bmu_s[8*j + 2*t],  bm1 = bmu_s[8*j + 2*t + 1];
    float bs0 = bsig_s[8*j + 2*t], bs1 = bsig_s[8*j + 2*t + 1];
    float t0 = ds[0] + bs0, t1 = ds[1] + bs1, t2 = ds[2] + bs0, t3 = ds[3] + bs1;
    float e0 = __expf(-t0), e1 = __expf(-t1), e2 = __expf(-t2), e3 = __expf(-t3);
    float u0 = 1.f + e0, u1 = 1.f + e1, u2 = 1.f + e2, u3 = 1.f + e3;
    zo[0] = zo[0] * rcpa(u0) + (dm[0] + bm0);
    zo[1] = zo[1] * rcpa(u1) + (dm[1] + bm1);
    zo[2] = zo[2] * rcpa(u2) + (dm[2] + bm0);
    zo[3] = zo[3] * rcpa(u3) + (dm[3] + bm1);
    ldA -= __logf(u0) + __logf(u1);          // rows g / g+8 split
    ldB -= __logf(u2) + __logf(u3);
}

// One coupling half-step. zin/zout are D-layout frags [octet j][4]:
// elems (g, 8j+2t), (g, 8j+2t+1), (g+8, ...), (g+8, ...). All A fragments are
// built in registers (D-frag layout == A-frag layout, octet j == k-octet j).
__device__ __forceinline__ void coupling(
    float (&zin)[8][4], float (&zout)[8][4], int s,
    uint32_t sb, char* smem, int lane, float& ldA, float& ldB)
{
    const int t = lane & 3;
    const uint32_t W0s  = sb + W0_OFF  + s*14336;
    const uint32_t W12s = sb + W12_OFF + s*32768;
    const float* bin_s  = (const float*)(smem + BIN_OFF)  + s*64;
    const float* bmu_s  = (const float*)(smem + BMU_OFF)  + s*64;
    const float* bsig_s = (const float*)(smem + BSIG_OFF) + s*64;

    // A frags (hi/lo) from zin, in registers
    uint32_t aH[4][4], aL[4][4];
#pragma unroll
    for (int kc = 0; kc < 4; kc++) {
        packhl(zin[2*kc  ][0], zin[2*kc  ][1], aH[kc][0], aL[kc][0]);
        packhl(zin[2*kc  ][2], zin[2*kc  ][3], aH[kc][1], aL[kc][1]);
        packhl(zin[2*kc+1][0], zin[2*kc+1][1], aH[kc][2], aL[kc][2]);
        packhl(zin[2*kc+1][2], zin[2*kc+1][3], aH[kc][3], aL[kc][3]);
    }

    // GEMM1: D1 = Z @ W0^T, n-tiles j=0..6; tanh; H frags built in registers
    uint32_t hH[4][4], hL[4][4];
#pragma unroll
    for (int p = 0; p < 3; p++) {           // tiles 2p, 2p+1
        float d0a[4]={0,0,0,0}, d0b[4]={0,0,0,0};
        float d1a[4]={0,0,0,0}, d1b[4]={0,0,0,0};
#pragma unroll
        for (int kc = 0; kc < 4; kc++) {
            uint32_t bh[4], bl[4];
            ldm_x4(bh, b_addr4(W0s, lane, 16*p, 2*kc));
            mma16816(d0a, aH[kc], bh);     mma16816(d1a, aH[kc], bh + 2);
            mma16816(d0b, aL[kc], bh);     mma16816(d1b, aL[kc], bh + 2);
            ldm_x4(bl, b_addr4(W0s, lane, 16*p, 8 + 2*kc));
            mma16816(d0b, aH[kc], bl);     mma16816(d1b, aH[kc], bl + 2);
        }
        int j0 = 2*p, j1 = 2*p + 1;
        float b00 = bin_s[8*j0 + 2*t], b01 = bin_s[8*j0 + 2*t + 1];
        float b10 = bin_s[8*j1 + 2*t], b11 = bin_s[8*j1 + 2*t + 1];
        float v0 = tanh_fast(d0a[0] + d0b[0] + b00);
        float v1 = tanh_fast(d0a[1] + d0b[1] + b01);
        float v2 = tanh_fast(d0a[2] + d0b[2] + b00);
        float v3 = tanh_fast(d0a[3] + d0b[3] + b01);
        float w0 = tanh_fast(d1a[0] + d1b[0] + b10);
        float w1 = tanh_fast(d1a[1] + d1b[1] + b11);
        float w2 = tanh_fast(d1a[2] + d1b[2] + b10);
        float w3 = tanh_fast(d1a[3] + d1b[3] + b11);
        packhl(v0, v1, hH[p][0], hL[p][0]);
        packhl(v2, v3, hH[p][1], hL[p][1]);
        packhl(w0, w1, hH[p][2], hL[p][2]);
        packhl(w2, w3, hH[p][3], hL[p][3]);
    }
    {   // n-tile 6 (h cols 48-55; 50-55 = 0 via zero W0 rows + zero bias)
        float da[4]={0,0,0,0}, db[4]={0,0,0,0};
#pragma unroll
        for (int kc = 0; kc < 4; kc++) {
            uint32_t bh[2], bl[2];
            ldm_x2(bh, b_addr2(W0s, lane, 48, 2*kc));
            mma16816(da, aH[kc], bh);
            mma16816(db, aL[kc], bh);
            ldm_x2(bl, b_addr2(W0s, lane, 48, 8 + 2*kc));
            mma16816(db, aH[kc], bl);
        }
        float b0 = bin_s[48 + 2*t], b1 = bin_s[48 + 2*t + 1];
        float v0 = tanh_fast(da[0] + db[0] + b0);
        float v1 = tanh_fast(da[1] + db[1] + b1);
        float v2 = tanh_fast(da[2] + db[2] + b0);
        float v3 = tanh_fast(da[3] + db[3] + b1);
        packhl(v0, v1, hH[3][0], hL[3][0]);
        packhl(v2, v3, hH[3][1], hL[3][1]);
        hH[3][2] = 0u; hH[3][3] = 0u;       // octet 7 = zero pad
        hL[3][2] = 0u; hL[3][3] = 0u;
    }

    // GEMM2: [MU|SIG] = H @ [W_mu;W_sig]^T
#pragma unroll
    for (int p = 0; p < 4; p++) {           // output tiles 2p, 2p+1 (of 8)
        float m0a[4]={0,0,0,0}, m0b[4]={0,0,0,0}, m1a[4]={0,0,0,0}, m1b[4]={0,0,0,0};
        float s0a[4]={0,0,0,0}, s0b[4]={0,0,0,0}, s1a[4]={0,0,0,0}, s1b[4]={0,0,0,0};
#pragma unroll
        for (int kc = 0; kc < 4; kc++) {
            uint32_t bmh[4], bsh[4], bml[4], bsl[4];
            ldm_x4(bmh, b_addr4(W12s, lane, 16*p,      2*kc));
            ldm_x4(bsh, b_addr4(W12s, lane, 64 + 16*p, 2*kc));
            mma16816(m0a, hH[kc], bmh);   mma16816(m1a, hH[kc], bmh + 2);
            mma16816(s0a, hH[kc], bsh);   mma16816(s1a, hH[kc], bsh + 2);
            mma16816(m0b, hL[kc], bmh);   mma16816(m1b, hL[kc], bmh + 2);
            mma16816(s0b, hL[kc], bsh);   mma16816(s1b, hL[kc], bsh + 2);
            ldm_x4(bml, b_addr4(W12s, lane, 16*p,      8 + 2*kc));
            ldm_x4(bsl, b_addr4(W12s, lane, 64 + 16*p, 8 + 2*kc));
            mma16816(m0b, hH[kc], bml);   mma16816(m1b, hH[kc], bml + 2);
            mma16816(s0b, hH[kc], bsl);   mma16816(s1b, hH[kc], bsl + 2);
        }
        float dm0[4], dm1[4], ds0[4], ds1[4];
#pragma unroll
        for (int i = 0; i < 4; i++) {
            dm0[i] = m0a[i] + m0b[i];  dm1[i] = m1a[i] + m1b[i];
            ds0[i] = s0a[i] + s0b[i];  ds1[i] = s1a[i] + s1b[i];
        }
        sig_update(zout[2*p],     dm0, ds0, 2*p,     bmu_s, bsig_s, t, ldA, ldB);
        sig_update(zout[2*p + 1], dm1, ds1, 2*p + 1, bmu_s, bsig_s, t, ldA, ldB);
    }
}

__global__ void __launch_bounds__(NT, 1) flow_kernel(
    const float* __restrict__ g_mean, const float* __restrict__ g_logvar,
    const float* __restrict__ g_eps,
    const float* __restrict__ g_Win,  const float* __restrict__ g_bin,
    const float* __restrict__ g_Wmu,  const float* __restrict__ g_bmu,
    const float* __restrict__ g_Wsig, const float* __restrict__ g_bsig,
    float* __restrict__ g_out)
{
    extern __shared__ char smem[];
    const uint32_t sb = smem_u32(smem);
    const int tid  = threadIdx.x;
    const int warp = tid >> 5, lane = tid & 31;
    const int g = lane >> 2, t = lane & 3;

    // zero whole SMEM (covers all pads), then stage weights hi/lo + biases
    for (int i = tid; i < SMEM_TOTAL/4; i += NT) ((uint32_t*)smem)[i] = 0u;
    __syncthreads();
    for (int i = tid; i < 4*50*64; i += NT) {                 // W_in [s][j][k]
        int s = i / 3200, r = i - s*3200, j = r >> 6, k = r & 63;
        store_w(smem, W0_OFF + s*14336, j, k, g_Win[i]);
    }
    for (int i = tid; i < 4*128*50; i += NT) {                // W_mu / W_sig rows
        int s = i / 6400, r = i - s*6400, o = r / 50, k = r - o*50;
        float v = (o < 64) ? g_Wmu[s*3200 + o*50 + k] : g_Wsig[s*3200 + (o-64)*50 + k];
        store_w(smem, W12_OFF + s*32768, o, k, v);
    }
    for (int i = tid; i < 200; i += NT) {
        int s = i / 50, j = i - s*50;
        ((float*)(smem + BIN_OFF))[s*64 + j] = g_bin[i];
    }
    for (int i = tid; i < 256; i += NT) {
        ((float*)(smem + BMU_OFF))[i]  = g_bmu[i];
        ((float*)(smem + BSIG_OFF))[i] = g_bsig[i];
    }
    __syncthreads();

    const size_t rowA = (size_t)blockIdx.x*128 + warp*16 + g;
    const size_t rowB = rowA + 8;

    // prologue: z frags (D layout) + logqz0 partials per row-half
    float z1[8][4], z2[8][4];
    float partA = 0.f, partB = 0.f;
#pragma unroll
    for (int j = 0; j < 8; j++) {
        int c1 = 8*j + 2*t, c2 = 64 + c1;
        float2 m, l, e;
        m = *(const float2*)(g_mean + rowA*128 + c1);
        l = *(const float2*)(g_logvar + rowA*128 + c1);
        e = *(const float2*)(g_eps + rowA*128 + c1);
        z1[j][0] = e.x*__expf(0.5f*l.x) + m.x;  z1[j][1] = e.y*__expf(0.5f*l.y) + m.y;
        partA += l.x + l.y + e.x*e.x + e.y*e.y;
        m = *(const float2*)(g_mean + rowB*128 + c1);
        l = *(const float2*)(g_logvar + rowB*128 + c1);
        e = *(const float2*)(g_eps + rowB*128 + c1);
        z1[j][2] = e.x*__expf(0.5f*l.x) + m.x;  z1[j][3] = e.y*__expf(0.5f*l.y) + m.y;
        partB += l.x + l.y + e.x*e.x + e.y*e.y;
        m = *(const float2*)(g_mean + rowA*128 + c2);
        l = *(const float2*)(g_logvar + rowA*128 + c2);
        e = *(const float2*)(g_eps + rowA*128 + c2);
        z2[j][0] = e.x*__expf(0.5f*l.x) + m.x;  z2[j][1] = e.y*__expf(0.5f*l.y) + m.y;
        partA += l.x + l.y + e.x*e.x + e.y*e.y;
        m = *(const float2*)(g_mean + rowB*128 + c2);
        l = *(const float2*)(g_logvar + rowB*128 + c2);
        e = *(const float2*)(g_eps + rowB*128 + c2);
        z2[j][2] = e.x*__expf(0.5f*l.x) + m.x;  z2[j][3] = e.y*__expf(0.5f*l.y) + m.y;
        partB += l.x + l.y + e.x*e.x + e.y*e.y;
    }

    float ldA = 0.f, ldB = 0.f;
#pragma unroll 1   // rolled: bounds I-cache to 2 coupling bodies
    for (int f = 0; f < 2; f++) {
        coupling(z1, z2, 2*f,     sb, smem, lane, ldA, ldB);
        coupling(z2, z1, 2*f + 1, sb, smem, lane, ldA, ldB);
    }

    // epilogue: write z, reduce logpz/logqz across the quad (lanes sharing g)
    float sqA = 0.f, sqB = 0.f;
#pragma unroll
    for (int j = 0; j < 8; j++) {
        int c1 = 8*j + 2*t, c2 = 64 + c1;
        *(float2*)(g_out + rowA*128 + c1) = make_float2(z1[j][0], z1[j][1]);
        *(float2*)(g_out + rowB*128 + c1) = make_float2(z1[j][2], z1[j][3]);
        *(float2*)(g_out + rowA*128 + c2) = make_float2(z2[j][0], z2[j][1]);
        *(float2*)(g_out + rowB*128 + c2) = make_float2(z2[j][2], z2[j][3]);
        sqA += z1[j][0]*z1[j][0] + z1[j][1]*z1[j][1]
             + z2[j][0]*z2[j][0] + z2[j][1]*z2[j][1];
        sqB += z1[j][2]*z1[j][2] + z1[j][3]*z1[j][3]
             + z2[j][2]*z2[j][2] + z2[j][3]*z2[j][3];
    }
#pragma unroll
    for (int d = 1; d <= 2; d <<= 1) {
        sqA   += __shfl_xor_sync(0xffffffffu, sqA, d);
        sqB   += __shfl_xor_sync(0xffffffffu, sqB, d);
        partA += __shfl_xor_sync(0xffffffffu, partA, d);
        partB += __shfl_xor_sync(0xffffffffu, partB, d);
        ldA   += __shfl_xor_sync(0xffffffffu, ldA, d);
        ldB   += __shfl_xor_sync(0xffffffffu, ldB, d);
    }
    if (t == 0) {
        g_out[(size_t)NB*128 + rowA]      = -0.5f * sqA;
        g_out[(size_t)NB*128 + NB + rowA] = -0.5f * partA - ldA;
        g_out[(size_t)NB*128 + rowB]      = -0.5f * sqB;
        g_out[(size_t)NB*128 + NB + rowB] = -0.5f * partB - ldB;
    }
}

extern "C" void kernel_launch(void* const* d_in, const int* in_sizes, int n_in,
                              void* d_out, int out_size)
{
    (void)in_sizes; (void)n_in; (void)out_size;
    cudaFuncSetAttribute(flow_kernel,
                         cudaFuncAttributeMaxDynamicSharedMemorySize, SMEM_TOTAL);
    flow_kernel<<<GRID, NT, SMEM_TOTAL>>>(
        (const float*)d_in[0], (const float*)d_in[1], (const float*)d_in[2],
        (const float*)d_in[3], (const float*)d_in[4], (const float*)d_in[5],
        (const float*)d_in[6], (const float*)d_in[7], (const float*)d_in[8],
        (float*)d_out);
}

// round 15
// speedup vs baseline: 2.3720x; 1.0242x over previous
#include <cuda_runtime.h>
#include <cuda_bf16.h>
#include <cstdint>

#define NB    262144
#define NT    256            // 8 warps x 16 rows = 128 rows/CTA
#define GRID  2048

// Weight rows: 272B linear stride (no swizzle; 272 ≡ 4 words mod 32 banks ->
// 8-row ldmatrix groups are conflict-free). 16 chunks of 16B per row:
// chunks 0-7 hi bf16 (k 0-63), chunks 8-15 lo (residual) bf16.
#define W0_OFF   0           // 4 stages x 56 rows x 272B (W_in as [n=j][k])
#define W0_STG   15232
#define W12_OFF  60928       // 4 stages x 128 rows x 272B (0-63 W_mu, 64-127 W_sig)
#define W12_STG  34816
#define BIN_OFF  200192      // f32 [4][64]
#define BMU_OFF  201216      // f32 [4][64]
#define BSIG_OFF 202240      // f32 [4][64]
#define SMEM_TOTAL 203264

__device__ __forceinline__ uint32_t smem_u32(const void* p) {
    uint32_t a;
    asm("{ .reg .u64 t; cvta.to.shared.u64 t, %1; cvt.u32.u64 %0, t; }" : "=r"(a) : "l"(p));
    return a;
}
__device__ __forceinline__ float rcpa(float x) {
    float r; asm("rcp.approx.f32 %0,%1;" : "=f"(r) : "f"(x)); return r;
}
__device__ __forceinline__ float tanh_fast(float x) {   // 2*sigmoid(2x)-1
    float e = __expf(-2.0f * x);
    return __fmaf_rn(2.0f, rcpa(1.0f + e), -1.0f);
}

__device__ __forceinline__ void mma16816(float* d, const uint32_t* a, const uint32_t* b) {
    asm volatile("mma.sync.aligned.m16n8k16.row.col.f32.bf16.bf16.f32 "
        "{%0,%1,%2,%3}, {%4,%5,%6,%7}, {%8,%9}, {%0,%1,%2,%3};"
        : "+f"(d[0]), "+f"(d[1]), "+f"(d[2]), "+f"(d[3])
        : "r"(a[0]), "r"(a[1]), "r"(a[2]), "r"(a[3]), "r"(b[0]), "r"(b[1]));
}
__device__ __forceinline__ void ldm_x4(uint32_t* r, uint32_t a) {
    asm volatile("ldmatrix.sync.aligned.m8n8.x4.shared.b16 {%0,%1,%2,%3}, [%4];"
        : "=r"(r[0]), "=r"(r[1]), "=r"(r[2]), "=r"(r[3]) : "r"(a));
}
__device__ __forceinline__ void ldm_x2(uint32_t* r, uint32_t a) {
    asm volatile("ldmatrix.sync.aligned.m8n8.x2.shared.b16 {%0,%1}, [%2];"
        : "=r"(r[0]), "=r"(r[1]) : "r"(a));
}

// pack (x,y) into hi-bf16x2 h and residual-lo-bf16x2 l (low half = x)
__device__ __forceinline__ void packhl(float x, float y, uint32_t &h, uint32_t &l) {
    asm("cvt.rn.bf16x2.f32 %0, %1, %2;" : "=r"(h) : "f"(y), "f"(x));
    float h0 = __uint_as_float(h << 16);
    float h1 = __uint_as_float(h & 0xffff0000u);
    asm("cvt.rn.bf16x2.f32 %0, %1, %2;" : "=r"(l) : "f"(y - h1), "f"(x - h0));
}

// weight element -> hi/lo bf16 at linear [row][chunk] position
__device__ __forceinline__ void store_w(char* smem, int base, int row, int k, float v) {
    __nv_bfloat16 hb = __float2bfloat16(v);
    __nv_bfloat16 lb = __float2bfloat16(v - __bfloat162float(hb));
    char* r = smem + base + row*272 + ((k >> 3) << 4) + (k & 7)*2;
    *(__nv_bfloat16*)(r)       = hb;
    *(__nv_bfloat16*)(r + 128) = lb;     // lo chunk = hi chunk + 8 -> +128B
}

__device__ __forceinline__ void sig_update(float* zo, const float* dm, const float* ds,
                                           int j, const float* bmu_s, const float* bsig_s,
                                           int t, float& ldA, float& ldB) {
    float bm0 = bmu_s[8*j + 2*t],  bm1 = bmu_s[8*j + 2*t + 1];
    float bs0 = bsig_s[8*j + 2*t], bs1 = bsig_s[8*j + 2*t + 1];
    float t0 = ds[0] + bs0, t1 = ds[1] + bs1, t2 = ds[2] + bs0, t3 = ds[3] + bs1;
    float e0 = __expf(-t0), e1 = __expf(-t1), e2 = __expf(-t2), e3 = __expf(-t3);
    float u0 = 1.f + e0, u1 = 1.f + e1, u2 = 1.f + e2, u3 = 1.f + e3;
    zo[0] = zo[0] * rcpa(u0) + (dm[0] + bm0);
    zo[1] = zo[1] * rcpa(u1) + (dm[1] + bm1);
    zo[2] = zo[2] * rcpa(u2) + (dm[2] + bm0);
    zo[3] = zo[3] * rcpa(u3) + (dm[3] + bm1);
    ldA -= __logf(u0) + __logf(u1);          // rows g / g+8 split
    ldB -= __logf(u2) + __logf(u3);
}

// One coupling half-step. zin/zout are D-layout frags [octet j][4]. A and H
// fragments built entirely in registers (D-frag layout == A-frag layout).
// brow4/brow2: per-thread lane base offsets for ldmatrix x4/x2 addressing.
__device__ __forceinline__ void coupling(
    float (&zin)[8][4], float (&zout)[8][4], int s,
    uint32_t sb, char* smem, int lane, uint32_t brow4, uint32_t brow2,
    float& ldA, float& ldB)
{
    const int t = lane & 3;
    const uint32_t W0b  = sb + W0_OFF  + s*W0_STG  + brow4;
    const uint32_t W12b = sb + W12_OFF + s*W12_STG + brow4;
    const float* bin_s  = (const float*)(smem + BIN_OFF)  + s*64;
    const float* bmu_s  = (const float*)(smem + BMU_OFF)  + s*64;
    const float* bsig_s = (const float*)(smem + BSIG_OFF) + s*64;

    // A frags (hi/lo) from zin, in registers
    uint32_t aH[4][4], aL[4][4];
#pragma unroll
    for (int kc = 0; kc < 4; kc++) {
        packhl(zin[2*kc  ][0], zin[2*kc  ][1], aH[kc][0], aL[kc][0]);
        packhl(zin[2*kc  ][2], zin[2*kc  ][3], aH[kc][1], aL[kc][1]);
        packhl(zin[2*kc+1][0], zin[2*kc+1][1], aH[kc][2], aL[kc][2]);
        packhl(zin[2*kc+1][2], zin[2*kc+1][3], aH[kc][3], aL[kc][3]);
    }

    // GEMM1: D1 = Z @ W0^T, n-tiles j=0..6; tanh; H frags in registers
    uint32_t hH[4][4], hL[4][4];
#pragma unroll
    for (int p = 0; p < 3; p++) {           // tiles 2p, 2p+1
        float d0a[4]={0,0,0,0}, d0b[4]={0,0,0,0};
        float d1a[4]={0,0,0,0}, d1b[4]={0,0,0,0};
        uint32_t ph = W0b + p*(16*272);     // hi chunks, walking
        uint32_t pl = ph + 128;             // lo chunks
#pragma unroll
        for (int kc = 0; kc < 4; kc++) {
            uint32_t bh[4], bl[4];
            ldm_x4(bh, ph); ph += 32;
            mma16816(d0a, aH[kc], bh);     mma16816(d1a, aH[kc], bh + 2);
            mma16816(d0b, aL[kc], bh);     mma16816(d1b, aL[kc], bh + 2);
            ldm_x4(bl, pl); pl += 32;
            mma16816(d0b, aH[kc], bl);     mma16816(d1b, aH[kc], bl + 2);
        }
        int j0 = 2*p, j1 = 2*p + 1;
        float b00 = bin_s[8*j0 + 2*t], b01 = bin_s[8*j0 + 2*t + 1];
        float b10 = bin_s[8*j1 + 2*t], b11 = bin_s[8*j1 + 2*t + 1];
        float v0 = tanh_fast(d0a[0] + d0b[0] + b00);
        float v1 = tanh_fast(d0a[1] + d0b[1] + b01);
        float v2 = tanh_fast(d0a[2] + d0b[2] + b00);
        float v3 = tanh_fast(d0a[3] + d0b[3] + b01);
        float w0 = tanh_fast(d1a[0] + d1b[0] + b10);
        float w1 = tanh_fast(d1a[1] + d1b[1] + b11);
        float w2 = tanh_fast(d1a[2] + d1b[2] + b10);
        float w3 = tanh_fast(d1a[3] + d1b[3] + b11);
        packhl(v0, v1, hH[p][0], hL[p][0]);
        packhl(v2, v3, hH[p][1], hL[p][1]);
        packhl(w0, w1, hH[p][2], hL[p][2]);
        packhl(w2, w3, hH[p][3], hL[p][3]);
    }
    {   // n-tile 6 (h cols 48-55; 50-55 = 0 via zero W0 rows + zero bias)
        float da[4]={0,0,0,0}, db[4]={0,0,0,0};
        uint32_t ph = sb + W0_OFF + s*W0_STG + brow2 + 48*272;
        uint32_t pl = ph + 128;
#pragma unroll
        for (int kc = 0; kc < 4; kc++) {
            uint32_t bh[2], bl[2];
            ldm_x2(bh, ph); ph += 32;
            mma16816(da, aH[kc], bh);
            mma16816(db, aL[kc], bh);
            ldm_x2(bl, pl); pl += 32;
            mma16816(db, aH[kc], bl);
        }
        float b0 = bin_s[48 + 2*t], b1 = bin_s[48 + 2*t + 1];
        float v0 = tanh_fast(da[0] + db[0] + b0);
        float v1 = tanh_fast(da[1] + db[1] + b1);
        float v2 = tanh_fast(da[2] + db[2] + b0);
        float v3 = tanh_fast(da[3] + db[3] + b1);
        packhl(v0, v1, hH[3][0], hL[3][0]);
        packhl(v2, v3, hH[3][1], hL[3][1]);
        hH[3][2] = 0u; hH[3][3] = 0u;       // octet 7 = zero pad
        hL[3][2] = 0u; hL[3][3] = 0u;
    }

    // GEMM2: [MU|SIG] = H @ [W_mu;W_sig]^T
#pragma unroll
    for (int p = 0; p < 4; p++) {           // output tiles 2p, 2p+1 (of 8)
        float m0a[4]={0,0,0,0}, m0b[4]={0,0,0,0}, m1a[4]={0,0,0,0}, m1b[4]={0,0,0,0};
        float s0a[4]={0,0,0,0}, s0b[4]={0,0,0,0}, s1a[4]={0,0,0,0}, s1b[4]={0,0,0,0};
        uint32_t pmh = W12b + p*(16*272);
        uint32_t psh = pmh + 64*272;
        uint32_t pml = pmh + 128;
        uint32_t psl = psh + 128;
#pragma unroll
        for (int kc = 0; kc < 4; kc++) {
            uint32_t bmh[4], bsh[4], bml[4], bsl[4];
            ldm_x4(bmh, pmh); pmh += 32;
            ldm_x4(bsh, psh); psh += 32;
            mma16816(m0a, hH[kc], bmh);   mma16816(m1a, hH[kc], bmh + 2);
            mma16816(s0a, hH[kc], bsh);   mma16816(s1a, hH[kc], bsh + 2);
            mma16816(m0b, hL[kc], bmh);   mma16816(m1b, hL[kc], bmh + 2);
            mma16816(s0b, hL[kc], bsh);   mma16816(s1b, hL[kc], bsh + 2);
            ldm_x4(bml, pml); pml += 32;
            ldm_x4(bsl, psl); psl += 32;
            mma16816(m0b, hH[kc], bml);   mma16816(m1b, hH[kc], bml + 2);
            mma16816(s0b, hH[kc], bsl);   mma16816(s1b, hH[kc], bsl + 2);
        }
        float dm0[4], dm1[4], ds0[4], ds1[4];
#pragma unroll
        for (int i = 0; i < 4; i++) {
            dm0[i] = m0a[i] + m0b[i];  dm1[i] = m1a[i] + m1b[i];
            ds0[i] = s0a[i] + s0b[i];  ds1[i] = s1a[i] + s1b[i];
        }
        sig_update(zout[2*p],     dm0, ds0, 2*p,     bmu_s, bsig_s, t, ldA, ldB);
        sig_update(zout[2*p + 1], dm1, ds1, 2*p + 1, bmu_s, bsig_s, t, ldA, ldB);
    }
}

__global__ void __launch_bounds__(NT, 1) flow_kernel(
    const float* __restrict__ g_mean, const float* __restrict__ g_logvar,
    const float* __restrict__ g_eps,
    const float* __restrict__ g_Win,  const float* __restrict__ g_bin,
    const float* __restrict__ g_Wmu,  const float* __restrict__ g_bmu,
    const float* __restrict__ g_Wsig, const float* __restrict__ g_bsig,
    float* __restrict__ g_out)
{
    extern __shared__ char smem[];
    const uint32_t sb = smem_u32(smem);
    const int tid  = threadIdx.x;
    const int warp = tid >> 5, lane = tid & 31;
    const int g = lane >> 2, t = lane & 3;

    // per-thread ldmatrix lane bases (computed once)
    const uint32_t brow4 = ((lane & 7) + ((lane >> 4) << 3))*272 + ((lane >> 3) & 1)*16;
    const uint32_t brow2 = (lane & 7)*272 + ((lane >> 3) & 1)*16;

    // zero whole SMEM (covers all pads), then stage weights hi/lo + biases
    for (int i = tid; i < SMEM_TOTAL/4; i += NT) ((uint32_t*)smem)[i] = 0u;
    __syncthreads();
    for (int i = tid; i < 4*50*64; i += NT) {                 // W_in [s][j][k]
        int s = i / 3200, r = i - s*3200, j = r >> 6, k = r & 63;
        store_w(smem, W0_OFF + s*W0_STG, j, k, g_Win[i]);
    }
    for (int i = tid; i < 4*128*50; i += NT) {                // W_mu / W_sig rows
        int s = i / 6400, r = i - s*6400, o = r / 50, k = r - o*50;
        float v = (o < 64) ? g_Wmu[s*3200 + o*50 + k] : g_Wsig[s*3200 + (o-64)*50 + k];
        store_w(smem, W12_OFF + s*W12_STG, o, k, v);
    }
    for (int i = tid; i < 200; i += NT) {
        int s = i / 50, j = i - s*50;
        ((float*)(smem + BIN_OFF))[s*64 + j] = g_bin[i];
    }
    for (int i = tid; i < 256; i += NT) {
        ((float*)(smem + BMU_OFF))[i]  = g_bmu[i];
        ((float*)(smem + BSIG_OFF))[i] = g_bsig[i];
    }
    __syncthreads();

    const size_t rowA = (size_t)blockIdx.x*128 + warp*16 + g;
    const size_t rowB = rowA + 8;

    // prologue: z frags (D layout) + logqz0 partials per row-half
    float z1[8][4], z2[8][4];
    float partA = 0.f, partB = 0.f;
#pragma unroll
    for (int j = 0; j < 8; j++) {
        int c1 = 8*j + 2*t, c2 = 64 + c1;
        float2 m, l, e;
        m = *(const float2*)(g_mean + rowA*128 + c1);
        l = *(const float2*)(g_logvar + rowA*128 + c1);
        e = *(const float2*)(g_eps + rowA*128 + c1);
        z1[j][0] = e.x*__expf(0.5f*l.x) + m.x;  z1[j][1] = e.y*__expf(0.5f*l.y) + m.y;
        partA += l.x + l.y + e.x*e.x + e.y*e.y;
        m = *(const float2*)(g_mean + rowB*128 + c1);
        l = *(const float2*)(g_logvar + rowB*128 + c1);
        e = *(const float2*)(g_eps + rowB*128 + c1);
        z1[j][2] = e.x*__expf(0.5f*l.x) + m.x;  z1[j][3] = e.y*__expf(0.5f*l.y) + m.y;
        partB += l.x + l.y + e.x*e.x + e.y*e.y;
        m = *(const float2*)(g_mean + rowA*128 + c2);
        l = *(const float2*)(g_logvar + rowA*128 + c2);
        e = *(const float2*)(g_eps + rowA*128 + c2);
        z2[j][0] = e.x*__expf(0.5f*l.x) + m.x;  z2[j][1] = e.y*__expf(0.5f*l.y) + m.y;
        partA += l.x + l.y + e.x*e.x + e.y*e.y;
        m = *(const float2*)(g_mean + rowB*128 + c2);
        l = *(const float2*)(g_logvar + rowB*128 + c2);
        e = *(const float2*)(g_eps + rowB*128 + c2);
        z2[j][2] = e.x*__expf(0.5f*l.x) + m.x;  z2[j][3] = e.y*__expf(0.5f*l.y) + m.y;
        partB += l.x + l.y + e.x*e.x + e.y*e.y;
    }

    float ldA = 0.f, ldB = 0.f;
#pragma unroll 1   // rolled: bounds I-cache to 2 coupling bodies
    for (int f = 0; f < 2; f++) {
        coupling(z1, z2, 2*f,     sb, smem, lane, brow4, brow2, ldA, ldB);
        coupling(z2, z1, 2*f + 1, sb, smem, lane, brow4, brow2, ldA, ldB);
    }

    // epilogue: write z, reduce logpz/logqz across the quad (lanes sharing g)
    float sqA = 0.f, sqB = 0.f;
#pragma unroll
    for (int j = 0; j < 8; j++) {
        int c1 = 8*j + 2*t, c2 = 64 + c1;
        *(float2*)(g_out + rowA*128 + c1) = make_float2(z1[j][0], z1[j][1]);
        *(float2*)(g_out + rowB*128 + c1) = make_float2(z1[j][2], z1[j][3]);
        *(float2*)(g_out + rowA*128 + c2) = make_float2(z2[j][0], z2[j][1]);
        *(float2*)(g_out + rowB*128 + c2) = make_float2(z2[j][2], z2[j][3]);
        sqA += z1[j][0]*z1[j][0] + z1[j][1]*z1[j][1]
             + z2[j][0]*z2[j][0] + z2[j][1]*z2[j][1];
        sqB += z1[j][2]*z1[j][2] + z1[j][3]*z1[j][3]
             + z2[j][2]*z2[j][2] + z2[j][3]*z2[j][3];
    }
#pragma unroll
    for (int d = 1; d <= 2; d <<= 1) {
        sqA   += __shfl_xor_sync(0xffffffffu, sqA, d);
        sqB   += __shfl_xor_sync(0xffffffffu, sqB, d);
        partA += __shfl_xor_sync(0xffffffffu, partA, d);
        partB += __shfl_xor_sync(0xffffffffu, partB, d);
        ldA   += __shfl_xor_sync(0xffffffffu, ldA, d);
        ldB   += __shfl_xor_sync(0xffffffffu, ldB, d);
    }
    if (t == 0) {
        g_out[(size_t)NB*128 + rowA]      = -0.5f * sqA;
        g_out[(size_t)NB*128 + NB + rowA] = -0.5f * partA - ldA;
        g_out[(size_t)NB*128 + rowB]      = -0.5f * sqB;
        g_out[(size_t)NB*128 + NB + rowB] = -0.5f * partB - ldB;
    }
}

extern "C" void kernel_launch(void* const* d_in, const int* in_sizes, int n_in,
                              void* d_out, int out_size)
{
    (void)in_sizes; (void)n_in; (void)out_size;
    cudaFuncSetAttribute(flow_kernel,
                         cudaFuncAttributeMaxDynamicSharedMemorySize, SMEM_TOTAL);
    flow_kernel<<<GRID, NT, SMEM_TOTAL>>>(
        (const float*)d_in[0], (const float*)d_in[1], (const float*)d_in[2],
        (const float*)d_in[3], (const float*)d_in[4], (const float*)d_in[5],
        (const float*)d_in[6], (const float*)d_in[7], (const float*)d_in[8],
        (float*)d_out);
}